// round 7
// baseline (speedup 1.0000x reference)
#include <cuda_runtime.h>
#include <cstdint>

constexpr int Bc  = 2;
constexpr int Sc  = 4096;
constexpr int DMc = 768;
constexpr int Hc  = 12;
constexpr int HDc = 64;
constexpr int BSc = Bc * Sc;          // 8192 rows
constexpr int BHc = Bc * Hc;          // 24

// Device scratch (allocation-free contract)
// g_q: natural [bh][s][d], tf32, pre-scaled by log2(e)/64
// g_k: per row d-permuted: word = 8*(d>>3) + 2*(d&3) + ((d>>2)&1)
// g_v: per head tiled: tile t (64 keys) -> 32 pair-rows of 128 words:
//      addr = t*4096 + (4*((key>>3)&7) + (key&3))*128 + 2*d + ((key>>2)&1)
__device__ float g_q[(size_t)BHc * Sc * HDc];
__device__ float g_k[(size_t)BHc * Sc * HDc];
__device__ float g_v[(size_t)BHc * Sc * HDc];
__device__ float g_attn[(size_t)BSc * DMc];
__device__ float g_res[(size_t)BSc * DMc];

// ---------------------------------------------------------------------------
// helpers
// ---------------------------------------------------------------------------
__device__ __forceinline__ uint32_t f2tf(float x) {
    uint32_t r;
    asm volatile("cvt.rna.tf32.f32 %0, %1;" : "=r"(r) : "f"(x));
    return r;
}
__device__ __forceinline__ float f2tff(float x) { return __uint_as_float(f2tf(x)); }

__device__ __forceinline__ float ex2f(float x) {
    float r;
    asm("ex2.approx.ftz.f32 %0, %1;" : "=f"(r) : "f"(x));
    return r;
}

__device__ __forceinline__ void mma8(float c[4],
    uint32_t a0, uint32_t a1, uint32_t a2, uint32_t a3,
    uint32_t b0, uint32_t b1)
{
    asm volatile(
        "mma.sync.aligned.m16n8k8.row.col.f32.tf32.tf32.f32 "
        "{%0,%1,%2,%3},{%4,%5,%6,%7},{%8,%9},{%0,%1,%2,%3};"
        : "+f"(c[0]), "+f"(c[1]), "+f"(c[2]), "+f"(c[3])
        : "r"(a0), "r"(a1), "r"(a2), "r"(a3), "r"(b0), "r"(b1));
}

__device__ __forceinline__ void cp16(float* dst_smem, const float* src) {
    uint32_t d = (uint32_t)__cvta_generic_to_shared(dst_smem);
    asm volatile("cp.async.ca.shared.global [%0], [%1], 16;\n" :: "r"(d), "l"(src));
}
__device__ __forceinline__ void cp_commit() {
    asm volatile("cp.async.commit_group;\n");
}
template<int N> __device__ __forceinline__ void cp_wait() {
    asm volatile("cp.async.wait_group %0;\n" :: "n"(N));
}

// pair-permuted word offset within a 64-word K row
__device__ __forceinline__ int kw(int d) {
    return ((d >> 3) << 3) + ((d & 3) << 1) + ((d >> 2) & 1);
}

// ---------------------------------------------------------------------------
// Tensor-core GEMM: C[m][n] = sum_k A[m][k] * W[n][k] (+bias) (+RoPE / +resid)
// Tile 128x64, Kc=32, 256 threads = 8 warps, warp = 16 rows x 64 cols.
// mode: 0=q(rope, *log2e/64, tf32)  1=k(rope, tf32, permuted layout)
//       2=v(bias, tf32, tiled layout) 3=out(residual add -> g_res, fp32)
// ---------------------------------------------------------------------------
__global__ __launch_bounds__(256) void gemm_mma(
    const float* __restrict__ A, const float* __restrict__ W,
    const float* __restrict__ bias,
    const float* __restrict__ cosb, const float* __restrict__ sinb,
    const float* __restrict__ resid, int mode)
{
    __shared__ float Xs[128][36];
    __shared__ float Ws[64][36];

    const int tid  = threadIdx.x;
    const int lane = tid & 31, wrp = tid >> 5;
    const int g = lane >> 2, q = lane & 3;
    const int m0 = blockIdx.y * 128, n0 = blockIdx.x * 64;

    const float* Ap = (mode == 3) ? g_attn : A;

    const int tr  = tid >> 3;
    const int lc4 = (tid & 7) * 4;

    float4 xr[4], wr[2];
    #pragma unroll
    for (int p = 0; p < 4; p++)
        xr[p] = *(const float4*)&Ap[(size_t)(m0 + p * 32 + tr) * DMc + lc4];
    #pragma unroll
    for (int p = 0; p < 2; p++)
        wr[p] = *(const float4*)&W[(size_t)(n0 + p * 32 + tr) * DMc + lc4];

    float c[8][4] = {};

    for (int k0 = 0; k0 < DMc; k0 += 32) {
        #pragma unroll
        for (int p = 0; p < 4; p++)
            *(float4*)&Xs[p * 32 + tr][lc4] = make_float4(
                f2tff(xr[p].x), f2tff(xr[p].y), f2tff(xr[p].z), f2tff(xr[p].w));
        #pragma unroll
        for (int p = 0; p < 2; p++)
            *(float4*)&Ws[p * 32 + tr][lc4] = make_float4(
                f2tff(wr[p].x), f2tff(wr[p].y), f2tff(wr[p].z), f2tff(wr[p].w));
        __syncthreads();

        if (k0 + 32 < DMc) {
            #pragma unroll
            for (int p = 0; p < 4; p++)
                xr[p] = *(const float4*)&Ap[(size_t)(m0 + p * 32 + tr) * DMc + k0 + 32 + lc4];
            #pragma unroll
            for (int p = 0; p < 2; p++)
                wr[p] = *(const float4*)&W[(size_t)(n0 + p * 32 + tr) * DMc + k0 + 32 + lc4];
        }

        #pragma unroll
        for (int ks = 0; ks < 4; ks++) {
            int kk = ks * 8;
            uint32_t a0 = __float_as_uint(Xs[wrp * 16 + g    ][kk + q    ]);
            uint32_t a1 = __float_as_uint(Xs[wrp * 16 + g + 8][kk + q    ]);
            uint32_t a2 = __float_as_uint(Xs[wrp * 16 + g    ][kk + q + 4]);
            uint32_t a3 = __float_as_uint(Xs[wrp * 16 + g + 8][kk + q + 4]);
            #pragma unroll
            for (int nt = 0; nt < 8; nt++) {
                uint32_t b0 = __float_as_uint(Ws[nt * 8 + g][kk + q    ]);
                uint32_t b1 = __float_as_uint(Ws[nt * 8 + g][kk + q + 4]);
                mma8(c[nt], a0, a1, a2, a3, b0, b1);
            }
        }
        __syncthreads();
    }

    // ---- epilogue ----
    if (mode <= 1) {
        const int h = blockIdx.x;
        // q gets log2(e)/64 so flash can use ex2 directly (both 1/sqrt(hd) factors folded)
        const float post = (mode == 0) ? (1.4426950408889634f / 64.0f) : 1.0f;
        #pragma unroll
        for (int rr = 0; rr < 2; rr++) {
            int row = m0 + wrp * 16 + g + rr * 8;
            int bb = row >> 12, sg = row & (Sc - 1);
            size_t base = (((size_t)(bb * Hc + h)) * Sc + sg) * HDc;
            #pragma unroll
            for (int nt = 0; nt < 4; nt++) {
                int d = nt * 8 + q * 2;      // d in [0,32), even
                float lo0 = c[nt][rr * 2 + 0]     + bias[n0 + d];
                float lo1 = c[nt][rr * 2 + 1]     + bias[n0 + d + 1];
                float hi0 = c[nt + 4][rr * 2 + 0] + bias[n0 + d + 32];
                float hi1 = c[nt + 4][rr * 2 + 1] + bias[n0 + d + 33];
                float c0 = cosb[sg * HDc + d],     c1 = cosb[sg * HDc + d + 1];
                float s0 = sinb[sg * HDc + d],     s1 = sinb[sg * HDc + d + 1];
                float r0 = (lo0 * c0 - hi0 * s0) * post;
                float r1 = (lo1 * c1 - hi1 * s1) * post;
                float r2 = (hi0 * c0 + lo0 * s0) * post;
                float r3 = (hi1 * c1 + lo1 * s1) * post;
                if (mode == 0) {
                    *(float2*)&g_q[base + d]      = make_float2(f2tff(r0), f2tff(r1));
                    *(float2*)&g_q[base + d + 32] = make_float2(f2tff(r2), f2tff(r3));
                } else {
                    int w0 = kw(d);
                    int w2 = kw(d + 32);
                    g_k[base + w0]     = f2tff(r0);
                    g_k[base + w0 + 2] = f2tff(r1);
                    g_k[base + w2]     = f2tff(r2);
                    g_k[base + w2 + 2] = f2tff(r3);
                }
            }
        }
    } else if (mode == 2) {
        const int h = blockIdx.x;
        #pragma unroll
        for (int rr = 0; rr < 2; rr++) {
            int row = m0 + wrp * 16 + g + rr * 8;
            int bb = row >> 12, sg = row & (Sc - 1);
            // tiled-pair V layout
            int t   = sg >> 6;
            int ks3 = (sg >> 3) & 7;
            int hh  = (sg >> 2) & 1;
            int qk  = sg & 3;
            size_t base = ((size_t)(bb * Hc + h)) * Sc * HDc
                        + (size_t)t * 4096 + (4 * ks3 + qk) * 128 + hh;
            #pragma unroll
            for (int nt = 0; nt < 8; nt++) {
                int d = nt * 8 + q * 2;
                g_v[base + 2 * d]     = f2tff(c[nt][rr * 2 + 0] + bias[n0 + d]);
                g_v[base + 2 * d + 2] = f2tff(c[nt][rr * 2 + 1] + bias[n0 + d + 1]);
            }
        }
    } else {
        #pragma unroll
        for (int rr = 0; rr < 2; rr++) {
            int row = m0 + wrp * 16 + g + rr * 8;
            #pragma unroll
            for (int nt = 0; nt < 8; nt++) {
                int col = n0 + nt * 8 + q * 2;
                float2 r = *(const float2*)&resid[(size_t)row * DMc + col];
                *(float2*)&g_res[(size_t)row * DMc + col] =
                    make_float2(c[nt][rr * 2 + 0] + r.x, c[nt][rr * 2 + 1] + r.y);
            }
        }
    }
}

// ---------------------------------------------------------------------------
// tf32 flash attention. BM=128, BN=64. Grid (S/128, B*H), 256 threads.
// No max-subtraction (scores bounded ~0.25); Q frags hoisted to registers;
// K/V pre-permuted in gmem -> conflict-free LDS.64 B-fragments;
// cp.async double-buffered.
// K smem tile: 64 rows x 72 words.  V smem tile: 32 pair-rows x 136 words.
// ---------------------------------------------------------------------------
constexpr int KTW = 72;        // K smem row stride (words)
constexpr int VTW = 136;       // V smem pair-row stride (words)
constexpr int KT_SZ = 64 * KTW;    // 4608
constexpr int VT_SZ = 32 * VTW;    // 4352

__device__ __forceinline__ void ldk(const float* kb, int n0t, float* Kd, int tid) {
    #pragma unroll
    for (int p = 0; p < 4; p++) {
        int f = p * 256 + tid;
        int row = f >> 4, c4 = (f & 15) * 4;
        cp16(&Kd[row * KTW + c4], &kb[(size_t)(n0t + row) * HDc + c4]);
    }
}
__device__ __forceinline__ void ldv(const float* vb, int n0t, float* Vd, int tid) {
    const float* src = vb + (size_t)n0t * HDc;   // tile block base
    #pragma unroll
    for (int p = 0; p < 4; p++) {
        int f = p * 256 + tid;
        int pr = f >> 5, ch = (f & 31) * 4;
        cp16(&Vd[pr * VTW + ch], &src[pr * 128 + ch]);
    }
}

__global__ __launch_bounds__(256, 2) void flash_mma()
{
    extern __shared__ float sh[];
    float* K0 = sh;
    float* K1 = K0 + KT_SZ;
    float* V0 = K1 + KT_SZ;
    float* V1 = V0 + VT_SZ;

    const int tid  = threadIdx.x;
    const int lane = tid & 31, wrp = tid >> 5;
    const int g = lane >> 2, q = lane & 3;
    const int bh = blockIdx.y, m0 = blockIdx.x * 128;

    const float* qb = g_q + (size_t)bh * Sc * HDc;
    const float* kb = g_k + (size_t)bh * Sc * HDc;
    const float* vb = g_v + (size_t)bh * Sc * HDc;

    ldk(kb, 0, K0, tid);
    ldv(vb, 0, V0, tid);
    cp_commit();
    ldk(kb, 64, K1, tid);
    ldv(vb, 64, V1, tid);
    cp_commit();

    // Q fragments: loop-invariant, registers for the whole kernel
    uint32_t qa[8][4];
    {
        const float* qr0 = qb + (size_t)(m0 + wrp * 16 + g) * HDc;
        const float* qr1 = qr0 + 8 * HDc;
        #pragma unroll
        for (int ks = 0; ks < 8; ks++) {
            qa[ks][0] = __float_as_uint(qr0[ks * 8 + q]);
            qa[ks][1] = __float_as_uint(qr1[ks * 8 + q]);
            qa[ks][2] = __float_as_uint(qr0[ks * 8 + q + 4]);
            qa[ks][3] = __float_as_uint(qr1[ks * 8 + q + 4]);
        }
    }

    cp_wait<1>();
    __syncthreads();

    float o[8][4] = {};
    float ps0 = 0.f, ps1 = 0.f;

    const int srcA = q >> 1, srcB = srcA + 2;
    const bool odd = (q & 1);

    #pragma unroll 1
    for (int t = 0; t < Sc / 64; t++) {
        float* Ks = (t & 1) ? K1 : K0;
        float* Vs = (t & 1) ? V1 : V0;

        // S = Q K^T   (B-frags: one LDS.64 each, conflict-free)
        float s[8][4] = {};
        #pragma unroll
        for (int ks = 0; ks < 8; ks++) {
            #pragma unroll
            for (int nt = 0; nt < 8; nt++) {
                float2 b = *(float2*)&Ks[(nt * 8 + g) * KTW + ks * 8 + 2 * q];
                mma8(s[nt], qa[ks][0], qa[ks][1], qa[ks][2], qa[ks][3],
                     __float_as_uint(b.x), __float_as_uint(b.y));
            }
        }

        // exp (base-2; log2e folded into q) + partial sums; no max needed
        #pragma unroll
        for (int nt = 0; nt < 8; nt++) {
            float e0 = ex2f(s[nt][0]);
            float e1 = ex2f(s[nt][1]);
            float e2 = ex2f(s[nt][2]);
            float e3 = ex2f(s[nt][3]);
            ps0 += e0 + e1;
            ps1 += e2 + e3;
            s[nt][0] = f2tff(e0); s[nt][1] = f2tff(e1);
            s[nt][2] = f2tff(e2); s[nt][3] = f2tff(e3);
        }

        // O += P V  (P A-frags via intra-quad shuffles; V B-frags LDS.64)
        #pragma unroll
        for (int ks = 0; ks < 8; ks++) {
            float t0 = __shfl_sync(0xffffffffu, s[ks][0], srcA, 4);
            float t1 = __shfl_sync(0xffffffffu, s[ks][1], srcA, 4);
            float t2 = __shfl_sync(0xffffffffu, s[ks][2], srcA, 4);
            float t3 = __shfl_sync(0xffffffffu, s[ks][3], srcA, 4);
            float u0 = __shfl_sync(0xffffffffu, s[ks][0], srcB, 4);
            float u1 = __shfl_sync(0xffffffffu, s[ks][1], srcB, 4);
            float u2 = __shfl_sync(0xffffffffu, s[ks][2], srcB, 4);
            float u3 = __shfl_sync(0xffffffffu, s[ks][3], srcB, 4);
            uint32_t a0 = __float_as_uint(odd ? t1 : t0);
            uint32_t a1 = __float_as_uint(odd ? t3 : t2);
            uint32_t a2 = __float_as_uint(odd ? u1 : u0);
            uint32_t a3 = __float_as_uint(odd ? u3 : u2);
            #pragma unroll
            for (int nt = 0; nt < 8; nt++) {
                float2 b = *(float2*)&Vs[(4 * ks + q) * VTW + 2 * (nt * 8 + g)];
                mma8(o[nt], a0, a1, a2, a3,
                     __float_as_uint(b.x), __float_as_uint(b.y));
            }
        }

        if (t == Sc / 64 - 1) break;
        __syncthreads();
        if (t + 2 < Sc / 64) {
            float* Kd = (t & 1) ? K1 : K0;
            float* Vd = (t & 1) ? V1 : V0;
            ldk(kb, (t + 2) * 64, Kd, tid);
            ldv(vb, (t + 2) * 64, Vd, tid);
            cp_commit();
            cp_wait<1>();
        } else {
            cp_wait<0>();
        }
        __syncthreads();
    }

    // final softmax-denominator reduction (per row, 4 lanes)
    ps0 += __shfl_xor_sync(0xffffffffu, ps0, 1);
    ps0 += __shfl_xor_sync(0xffffffffu, ps0, 2);
    ps1 += __shfl_xor_sync(0xffffffffu, ps1, 1);
    ps1 += __shfl_xor_sync(0xffffffffu, ps1, 2);
    float inv0 = 1.0f / ps0, inv1 = 1.0f / ps1;

    const int b = bh / Hc, h = bh % Hc;
    #pragma unroll
    for (int rr = 0; rr < 2; rr++) {
        int row = m0 + wrp * 16 + g + rr * 8;
        float inv = rr ? inv1 : inv0;
        size_t base = ((size_t)(b * Sc + row)) * DMc + h * HDc;
        #pragma unroll
        for (int nt = 0; nt < 8; nt++) {
            *(float2*)&g_attn[base + nt * 8 + q * 2] =
                make_float2(o[nt][rr * 2] * inv, o[nt][rr * 2 + 1] * inv);
        }
    }
}

// ---------------------------------------------------------------------------
// LayerNorm: one block per row of 768
// ---------------------------------------------------------------------------
__global__ __launch_bounds__(256) void ln_kernel(
    const float* __restrict__ gam, const float* __restrict__ bet,
    float* __restrict__ out)
{
    const int row = blockIdx.x;
    const int tid = threadIdx.x;
    const float* x = g_res + (size_t)row * DMc;

    float v0 = x[tid], v1 = x[tid + 256], v2 = x[tid + 512];
    float s  = v0 + v1 + v2;
    float sq = v0 * v0 + v1 * v1 + v2 * v2;

    #pragma unroll
    for (int off = 16; off >= 1; off >>= 1) {
        s  += __shfl_xor_sync(0xffffffffu, s,  off);
        sq += __shfl_xor_sync(0xffffffffu, sq, off);
    }

    __shared__ float ws[8], wq[8];
    int w = tid >> 5, lane = tid & 31;
    if (lane == 0) { ws[w] = s; wq[w] = sq; }
    __syncthreads();
    s = 0.f; sq = 0.f;
    #pragma unroll
    for (int i = 0; i < 8; i++) { s += ws[i]; sq += wq[i]; }

    const float inv_n = 1.0f / 768.0f;
    float mu  = s * inv_n;
    float var = sq * inv_n - mu * mu;
    float inv = rsqrtf(var + 1e-12f);

    float* op = out + (size_t)row * DMc;
    op[tid]       = (v0 - mu) * inv * gam[tid]       + bet[tid];
    op[tid + 256] = (v1 - mu) * inv * gam[tid + 256] + bet[tid + 256];
    op[tid + 512] = (v2 - mu) * inv * gam[tid + 512] + bet[tid + 512];
}

// ---------------------------------------------------------------------------
extern "C" void kernel_launch(void* const* d_in, const int* in_sizes, int n_in,
                              void* d_out, int out_size)
{
    const float* hidden = (const float*)d_in[0];
    const float* cosb   = (const float*)d_in[1];
    const float* sinb   = (const float*)d_in[2];
    const float* Wq     = (const float*)d_in[3];
    const float* bq     = (const float*)d_in[4];
    const float* Wk     = (const float*)d_in[5];
    const float* bk     = (const float*)d_in[6];
    const float* Wv     = (const float*)d_in[7];
    const float* bv     = (const float*)d_in[8];
    const float* Wo     = (const float*)d_in[9];
    const float* lng    = (const float*)d_in[10];
    const float* lnb    = (const float*)d_in[11];
    float* out = (float*)d_out;

    dim3 gg(DMc / 64, BSc / 128);   // (12, 64)

    gemm_mma<<<gg, 256>>>(hidden, Wq, bq, cosb, sinb, nullptr, 0);
    gemm_mma<<<gg, 256>>>(hidden, Wk, bk, cosb, sinb, nullptr, 1);
    gemm_mma<<<gg, 256>>>(hidden, Wv, bv, cosb, sinb, nullptr, 2);

    const int flash_smem = (2 * KT_SZ + 2 * VT_SZ) * (int)sizeof(float);  // 71680
    cudaFuncSetAttribute(flash_mma,
                         cudaFuncAttributeMaxDynamicSharedMemorySize, flash_smem);
    flash_mma<<<dim3(Sc / 128, BHc), 256, flash_smem>>>();

    gemm_mma<<<gg, 256>>>(hidden, Wo, nullptr, cosb, sinb, hidden, 3);
    ln_kernel<<<BSc, 256>>>(lng, lnb, out);
}

// round 8
// speedup vs baseline: 2.0757x; 2.0757x over previous
#include <cuda_runtime.h>
#include <cstdint>

constexpr int Bc  = 2;
constexpr int Sc  = 4096;
constexpr int DMc = 768;
constexpr int Hc  = 12;
constexpr int HDc = 64;
constexpr int BSc = Bc * Sc;
constexpr int BHc = Bc * Hc;

// Scratch. q/k/v are bf16, packed as uint32 (bf16x2 words).
// g_qw: natural [bh][s][d/2], q pre-scaled by log2(e)/64.
// g_kw: per 64-key tile: word[(dp'>>3)*4+(dp'&3)][2*n+e]  (dp'=d-pair, e=(dp'>>2)&1)
// g_vw: per 64-key tile: word[(j>>3)*4+(j&3)][2*d+e]      (j=key-pair,  e=(j>>2)&1)
__device__ uint32_t g_qw[(size_t)BHc * Sc * 32];
__device__ uint32_t g_kw[(size_t)BHc * Sc * 32];
__device__ uint32_t g_vw[(size_t)BHc * Sc * 32];
__device__ float g_attn[(size_t)BSc * DMc];
__device__ float g_res[(size_t)BSc * DMc];

// ---------------------------------------------------------------------------
// helpers
// ---------------------------------------------------------------------------
__device__ __forceinline__ uint32_t f2tf(float x) {
    uint32_t r;
    asm volatile("cvt.rna.tf32.f32 %0, %1;" : "=r"(r) : "f"(x));
    return r;
}
__device__ __forceinline__ float f2tff(float x) { return __uint_as_float(f2tf(x)); }

__device__ __forceinline__ float ex2f(float x) {
    float r;
    asm("ex2.approx.ftz.f32 %0, %1;" : "=f"(r) : "f"(x));
    return r;
}

__device__ __forceinline__ uint32_t packbf(float lo, float hi) {
    uint32_t r;
    asm("cvt.rn.bf16x2.f32 %0, %1, %2;" : "=r"(r) : "f"(hi), "f"(lo));
    return r;
}

// tf32 m16n8k8 (GEMMs)
__device__ __forceinline__ void mma8(float c[4],
    uint32_t a0, uint32_t a1, uint32_t a2, uint32_t a3,
    uint32_t b0, uint32_t b1)
{
    asm volatile(
        "mma.sync.aligned.m16n8k8.row.col.f32.tf32.tf32.f32 "
        "{%0,%1,%2,%3},{%4,%5,%6,%7},{%8,%9},{%0,%1,%2,%3};"
        : "+f"(c[0]), "+f"(c[1]), "+f"(c[2]), "+f"(c[3])
        : "r"(a0), "r"(a1), "r"(a2), "r"(a3), "r"(b0), "r"(b1));
}

// bf16 m16n8k16 (flash)
__device__ __forceinline__ void mma16(float c[4],
    uint32_t a0, uint32_t a1, uint32_t a2, uint32_t a3,
    uint32_t b0, uint32_t b1)
{
    asm volatile(
        "mma.sync.aligned.m16n8k16.row.col.f32.bf16.bf16.f32 "
        "{%0,%1,%2,%3},{%4,%5,%6,%7},{%8,%9},{%0,%1,%2,%3};"
        : "+f"(c[0]), "+f"(c[1]), "+f"(c[2]), "+f"(c[3])
        : "r"(a0), "r"(a1), "r"(a2), "r"(a3), "r"(b0), "r"(b1));
}

__device__ __forceinline__ void cp16(void* dst_smem, const void* src) {
    uint32_t d = (uint32_t)__cvta_generic_to_shared(dst_smem);
    asm volatile("cp.async.ca.shared.global [%0], [%1], 16;\n" :: "r"(d), "l"(src));
}
__device__ __forceinline__ void cp_commit() {
    asm volatile("cp.async.commit_group;\n");
}
template<int N> __device__ __forceinline__ void cp_wait() {
    asm volatile("cp.async.wait_group %0;\n" :: "n"(N));
}

// ---------------------------------------------------------------------------
// tf32 GEMM: C[m][n] = sum_k A[m][k] * W[n][k] (+bias) (+RoPE / +resid)
// Tile 128x64, Kc=32, 8 warps. Double-buffered smem: ONE barrier per k-iter.
// mode: 0=q(rope,*log2e/64,bf16) 1=k(rope,bf16 tile layout)
//       2=v(bias,bf16 tile layout) 3=out(residual -> g_res, fp32)
// ---------------------------------------------------------------------------
__global__ __launch_bounds__(256) void gemm_mma(
    const float* __restrict__ A, const float* __restrict__ W,
    const float* __restrict__ bias,
    const float* __restrict__ cosb, const float* __restrict__ sinb,
    const float* __restrict__ resid, int mode)
{
    extern __shared__ float gsh[];
    // buffers: Xs[2][128][36], Ws[2][64][36]
    float* Xs[2] = { gsh, gsh + 128 * 36 + 64 * 36 };
    float* Ws[2] = { gsh + 128 * 36, gsh + 2 * (128 * 36) + 64 * 36 };

    const int tid  = threadIdx.x;
    const int lane = tid & 31, wrp = tid >> 5;
    const int g = lane >> 2, q = lane & 3;
    const int m0 = blockIdx.y * 128, n0 = blockIdx.x * 64;

    const float* Ap = (mode == 3) ? g_attn : A;

    const int tr  = tid >> 3;
    const int lc4 = (tid & 7) * 4;

    float4 xr[4], wr[2];
    #pragma unroll
    for (int p = 0; p < 4; p++)
        xr[p] = *(const float4*)&Ap[(size_t)(m0 + p * 32 + tr) * DMc + lc4];
    #pragma unroll
    for (int p = 0; p < 2; p++)
        wr[p] = *(const float4*)&W[(size_t)(n0 + p * 32 + tr) * DMc + lc4];

    float c[8][4] = {};
    int buf = 0;

    for (int k0 = 0; k0 < DMc; k0 += 32) {
        float* Xb = Xs[buf];
        float* Wb = Ws[buf];
        #pragma unroll
        for (int p = 0; p < 4; p++)
            *(float4*)&Xb[(p * 32 + tr) * 36 + lc4] = make_float4(
                f2tff(xr[p].x), f2tff(xr[p].y), f2tff(xr[p].z), f2tff(xr[p].w));
        #pragma unroll
        for (int p = 0; p < 2; p++)
            *(float4*)&Wb[(p * 32 + tr) * 36 + lc4] = make_float4(
                f2tff(wr[p].x), f2tff(wr[p].y), f2tff(wr[p].z), f2tff(wr[p].w));
        __syncthreads();

        if (k0 + 32 < DMc) {
            #pragma unroll
            for (int p = 0; p < 4; p++)
                xr[p] = *(const float4*)&Ap[(size_t)(m0 + p * 32 + tr) * DMc + k0 + 32 + lc4];
            #pragma unroll
            for (int p = 0; p < 2; p++)
                wr[p] = *(const float4*)&W[(size_t)(n0 + p * 32 + tr) * DMc + k0 + 32 + lc4];
        }

        #pragma unroll
        for (int ks = 0; ks < 4; ks++) {
            int kk = ks * 8;
            uint32_t a0 = __float_as_uint(Xb[(wrp * 16 + g    ) * 36 + kk + q    ]);
            uint32_t a1 = __float_as_uint(Xb[(wrp * 16 + g + 8) * 36 + kk + q    ]);
            uint32_t a2 = __float_as_uint(Xb[(wrp * 16 + g    ) * 36 + kk + q + 4]);
            uint32_t a3 = __float_as_uint(Xb[(wrp * 16 + g + 8) * 36 + kk + q + 4]);
            #pragma unroll
            for (int nt = 0; nt < 8; nt++) {
                uint32_t b0 = __float_as_uint(Wb[(nt * 8 + g) * 36 + kk + q    ]);
                uint32_t b1 = __float_as_uint(Wb[(nt * 8 + g) * 36 + kk + q + 4]);
                mma8(c[nt], a0, a1, a2, a3, b0, b1);
            }
        }
        buf ^= 1;
    }

    // ---- epilogue ----
    if (mode <= 1) {
        const int h = blockIdx.x;
        const float post = (mode == 0) ? (1.4426950408889634f / 64.0f) : 1.0f;
        #pragma unroll
        for (int rr = 0; rr < 2; rr++) {
            int row = m0 + wrp * 16 + g + rr * 8;
            int bb = row >> 12, sg = row & (Sc - 1);
            size_t hb = (size_t)(bb * Hc + h) * Sc * 32;
            #pragma unroll
            for (int nt = 0; nt < 4; nt++) {
                int d = nt * 8 + q * 2;      // [0,32), even
                float lo0 = c[nt][rr * 2 + 0]     + bias[n0 + d];
                float lo1 = c[nt][rr * 2 + 1]     + bias[n0 + d + 1];
                float hi0 = c[nt + 4][rr * 2 + 0] + bias[n0 + d + 32];
                float hi1 = c[nt + 4][rr * 2 + 1] + bias[n0 + d + 33];
                float c0 = cosb[sg * HDc + d],     c1 = cosb[sg * HDc + d + 1];
                float s0 = sinb[sg * HDc + d],     s1 = sinb[sg * HDc + d + 1];
                float r0 = (lo0 * c0 - hi0 * s0) * post;
                float r1 = (lo1 * c1 - hi1 * s1) * post;
                float r2 = (hi0 * c0 + lo0 * s0) * post;
                float r3 = (hi1 * c1 + lo1 * s1) * post;
                if (mode == 0) {
                    size_t base = hb + (size_t)sg * 32;
                    g_qw[base + nt * 4 + q]      = packbf(r0, r1);
                    g_qw[base + nt * 4 + q + 16] = packbf(r2, r3);
                } else {
                    int tile = sg >> 6, n = sg & 63;
                    size_t tb = hb + (size_t)tile * 2048;
                    int dp = nt * 4 + q;             // d/2 in [0,16)
                    int rrow = (dp >> 3) * 4 + (dp & 3);
                    int e = (dp >> 2) & 1;
                    g_kw[tb + rrow * 128 + 2 * n + e]        = packbf(r0, r1);
                    g_kw[tb + (rrow + 8) * 128 + 2 * n + e]  = packbf(r2, r3);  // dp+16
                }
            }
        }
    } else if (mode == 2) {
        const int h = blockIdx.x;
        #pragma unroll
        for (int rr = 0; rr < 2; rr++) {
            int row = m0 + wrp * 16 + g + rr * 8;
            int bb = row >> 12, sg = row & (Sc - 1);
            size_t hb = (size_t)(bb * Hc + h) * Sc * 32;
            int tile = sg >> 6;
            int jj = (sg >> 1) & 31;
            int rrow = (jj >> 3) * 4 + (jj & 3);
            int e = (jj >> 2) & 1;
            size_t bw = hb + (size_t)tile * 2048 + rrow * 128 + e;
            #pragma unroll
            for (int nt = 0; nt < 8; nt++) {
                int d = nt * 8 + q * 2;
                float v0 = c[nt][rr * 2 + 0] + bias[n0 + d];
                float v1 = c[nt][rr * 2 + 1] + bias[n0 + d + 1];
                float w0 = __shfl_down_sync(0xffffffffu, v0, 4);
                float w1 = __shfl_down_sync(0xffffffffu, v1, 4);
                if ((g & 1) == 0) {       // my key even -> low half; partner -> high
                    g_vw[bw + 2 * d]       = packbf(v0, w0);
                    g_vw[bw + 2 * (d + 1)] = packbf(v1, w1);
                }
            }
        }
    } else {
        #pragma unroll
        for (int rr = 0; rr < 2; rr++) {
            int row = m0 + wrp * 16 + g + rr * 8;
            #pragma unroll
            for (int nt = 0; nt < 8; nt++) {
                int col = n0 + nt * 8 + q * 2;
                float2 r = *(const float2*)&resid[(size_t)row * DMc + col];
                *(float2*)&g_res[(size_t)row * DMc + col] =
                    make_float2(c[nt][rr * 2 + 0] + r.x, c[nt][rr * 2 + 1] + r.y);
            }
        }
    }
}

// ---------------------------------------------------------------------------
// bf16 flash attention. BM=128, BN=64. Grid (S/128, B*H), 256 threads.
// No max-subtraction (scores bounded); Q frags in registers (16 regs);
// P-as-A (C frag of QK == A frag of PV, bf16 pack, zero shuffles);
// K/V tiles pre-packed in gmem, cp.async double-buffered, LDS.64 conflict-free.
// Tile in smem: 16 rows x 136 words (128 data + 8 pad).
// ---------------------------------------------------------------------------
constexpr int TSTRIDE = 136;
constexpr int TSZ = 16 * TSTRIDE;   // 2176 words per tile

__device__ __forceinline__ void ldt(const uint32_t* src_tile, uint32_t* dst, int tid) {
    #pragma unroll
    for (int p = 0; p < 2; p++) {
        int f = p * 256 + tid;            // 0..511
        int r = f >> 5, w4 = (f & 31) * 4;
        cp16(&dst[r * TSTRIDE + w4], &src_tile[f * 4]);
    }
}

__global__ __launch_bounds__(256, 2) void flash_mma()
{
    __shared__ uint32_t sh[4 * TSZ];
    uint32_t* K0 = sh;
    uint32_t* K1 = sh + TSZ;
    uint32_t* V0 = sh + 2 * TSZ;
    uint32_t* V1 = sh + 3 * TSZ;

    const int tid  = threadIdx.x;
    const int lane = tid & 31, wrp = tid >> 5;
    const int g = lane >> 2, q = lane & 3;
    const int bh = blockIdx.y, m0 = blockIdx.x * 128;

    const uint32_t* qw = g_qw + (size_t)bh * Sc * 32;
    const uint32_t* kw = g_kw + (size_t)bh * Sc * 32;
    const uint32_t* vw = g_vw + (size_t)bh * Sc * 32;

    ldt(kw, K0, tid);
    ldt(vw, V0, tid);
    cp_commit();
    ldt(kw + 2048, K1, tid);
    ldt(vw + 2048, V1, tid);
    cp_commit();

    // Q fragments (bf16x2 packed) — loop-invariant
    uint32_t qa[4][4];
    {
        const uint32_t* q0 = qw + (size_t)(m0 + wrp * 16 + g) * 32;
        const uint32_t* q1 = q0 + 8 * 32;
        #pragma unroll
        for (int ks = 0; ks < 4; ks++) {
            qa[ks][0] = q0[8 * ks + q];
            qa[ks][1] = q1[8 * ks + q];
            qa[ks][2] = q0[8 * ks + q + 4];
            qa[ks][3] = q1[8 * ks + q + 4];
        }
    }

    cp_wait<1>();
    __syncthreads();

    float o[8][4] = {};
    float ps0 = 0.f, ps1 = 0.f;

    #pragma unroll 1
    for (int t = 0; t < Sc / 64; t++) {
        uint32_t* Ks = (t & 1) ? K1 : K0;
        uint32_t* Vs = (t & 1) ? V1 : V0;

        // S = Q K^T
        float s[8][4] = {};
        #pragma unroll
        for (int ks = 0; ks < 4; ks++) {
            #pragma unroll
            for (int nt = 0; nt < 8; nt++) {
                uint2 b = *(uint2*)&Ks[(ks * 4 + q) * TSTRIDE + 2 * (nt * 8 + g)];
                mma16(s[nt], qa[ks][0], qa[ks][1], qa[ks][2], qa[ks][3], b.x, b.y);
            }
        }

        // exp2 (log2e folded in q) + partial sums + bf16 pack (P-as-A frags)
        uint32_t pk[8][2];
        #pragma unroll
        for (int nt = 0; nt < 8; nt++) {
            float e0 = ex2f(s[nt][0]);
            float e1 = ex2f(s[nt][1]);
            float e2 = ex2f(s[nt][2]);
            float e3 = ex2f(s[nt][3]);
            ps0 += e0 + e1;
            ps1 += e2 + e3;
            pk[nt][0] = packbf(e0, e1);   // row g,   cols 2q,2q+1
            pk[nt][1] = packbf(e2, e3);   // row g+8
        }

        // O += P V
        #pragma unroll
        for (int ks = 0; ks < 4; ks++) {
            #pragma unroll
            for (int nt = 0; nt < 8; nt++) {
                uint2 b = *(uint2*)&Vs[(ks * 4 + q) * TSTRIDE + 2 * (nt * 8 + g)];
                mma16(o[nt], pk[2 * ks][0], pk[2 * ks][1],
                             pk[2 * ks + 1][0], pk[2 * ks + 1][1], b.x, b.y);
            }
        }

        if (t == Sc / 64 - 1) break;
        __syncthreads();
        if (t + 2 < Sc / 64) {
            uint32_t* Kd = (t & 1) ? K1 : K0;
            uint32_t* Vd = (t & 1) ? V1 : V0;
            ldt(kw + (size_t)(t + 2) * 2048, Kd, tid);
            ldt(vw + (size_t)(t + 2) * 2048, Vd, tid);
            cp_commit();
            cp_wait<1>();
        } else {
            cp_wait<0>();
        }
        __syncthreads();
    }

    // softmax denominators (4 lanes per row)
    ps0 += __shfl_xor_sync(0xffffffffu, ps0, 1);
    ps0 += __shfl_xor_sync(0xffffffffu, ps0, 2);
    ps1 += __shfl_xor_sync(0xffffffffu, ps1, 1);
    ps1 += __shfl_xor_sync(0xffffffffu, ps1, 2);
    float inv0 = 1.0f / ps0, inv1 = 1.0f / ps1;

    const int b = bh / Hc, h = bh % Hc;
    #pragma unroll
    for (int rr = 0; rr < 2; rr++) {
        int row = m0 + wrp * 16 + g + rr * 8;
        float inv = rr ? inv1 : inv0;
        size_t base = ((size_t)(b * Sc + row)) * DMc + h * HDc;
        #pragma unroll
        for (int nt = 0; nt < 8; nt++) {
            *(float2*)&g_attn[base + nt * 8 + q * 2] =
                make_float2(o[nt][rr * 2] * inv, o[nt][rr * 2 + 1] * inv);
        }
    }
}

// ---------------------------------------------------------------------------
// LayerNorm: one block per row of 768
// ---------------------------------------------------------------------------
__global__ __launch_bounds__(256) void ln_kernel(
    const float* __restrict__ gam, const float* __restrict__ bet,
    float* __restrict__ out)
{
    const int row = blockIdx.x;
    const int tid = threadIdx.x;
    const float* x = g_res + (size_t)row * DMc;

    float v0 = x[tid], v1 = x[tid + 256], v2 = x[tid + 512];
    float s  = v0 + v1 + v2;
    float sq = v0 * v0 + v1 * v1 + v2 * v2;

    #pragma unroll
    for (int off = 16; off >= 1; off >>= 1) {
        s  += __shfl_xor_sync(0xffffffffu, s,  off);
        sq += __shfl_xor_sync(0xffffffffu, sq, off);
    }

    __shared__ float ws[8], wq[8];
    int w = tid >> 5, lane = tid & 31;
    if (lane == 0) { ws[w] = s; wq[w] = sq; }
    __syncthreads();
    s = 0.f; sq = 0.f;
    #pragma unroll
    for (int i = 0; i < 8; i++) { s += ws[i]; sq += wq[i]; }

    const float inv_n = 1.0f / 768.0f;
    float mu  = s * inv_n;
    float var = sq * inv_n - mu * mu;
    float inv = rsqrtf(var + 1e-12f);

    float* op = out + (size_t)row * DMc;
    op[tid]       = (v0 - mu) * inv * gam[tid]       + bet[tid];
    op[tid + 256] = (v1 - mu) * inv * gam[tid + 256] + bet[tid + 256];
    op[tid + 512] = (v2 - mu) * inv * gam[tid + 512] + bet[tid + 512];
}

// ---------------------------------------------------------------------------
extern "C" void kernel_launch(void* const* d_in, const int* in_sizes, int n_in,
                              void* d_out, int out_size)
{
    const float* hidden = (const float*)d_in[0];
    const float* cosb   = (const float*)d_in[1];
    const float* sinb   = (const float*)d_in[2];
    const float* Wq     = (const float*)d_in[3];
    const float* bq     = (const float*)d_in[4];
    const float* Wk     = (const float*)d_in[5];
    const float* bk     = (const float*)d_in[6];
    const float* Wv     = (const float*)d_in[7];
    const float* bv     = (const float*)d_in[8];
    const float* Wo     = (const float*)d_in[9];
    const float* lng    = (const float*)d_in[10];
    const float* lnb    = (const float*)d_in[11];
    float* out = (float*)d_out;

    dim3 gg(DMc / 64, BSc / 128);   // (12, 64)
    const int gemm_smem = 2 * (128 * 36 + 64 * 36) * (int)sizeof(float);  // 55296
    cudaFuncSetAttribute(gemm_mma,
                         cudaFuncAttributeMaxDynamicSharedMemorySize, gemm_smem);

    gemm_mma<<<gg, 256, gemm_smem>>>(hidden, Wq, bq, cosb, sinb, nullptr, 0);
    gemm_mma<<<gg, 256, gemm_smem>>>(hidden, Wk, bk, cosb, sinb, nullptr, 1);
    gemm_mma<<<gg, 256, gemm_smem>>>(hidden, Wv, bv, cosb, sinb, nullptr, 2);

    flash_mma<<<dim3(Sc / 128, BHc), 256>>>();

    gemm_mma<<<gg, 256, gemm_smem>>>(hidden, Wo, nullptr, cosb, sinb, hidden, 3);
    ln_kernel<<<BSc, 256>>>(lng, lnb, out);
}

// round 10
// speedup vs baseline: 2.6783x; 1.2903x over previous
#include <cuda_runtime.h>
#include <cstdint>

constexpr int Bc  = 2;
constexpr int Sc  = 4096;
constexpr int DMc = 768;
constexpr int Hc  = 12;
constexpr int HDc = 64;
constexpr int BSc = Bc * Sc;
constexpr int BHc = Bc * Hc;

// Scratch. q/k/v are bf16, packed as uint32 (bf16x2 words).
// g_qw: natural [bh][s][d/2], q pre-scaled by log2(e)/64.
// g_kw: per 64-key tile: word[(dp'>>3)*4+(dp'&3)][2*n+e]  (dp'=d-pair, e=(dp'>>2)&1)
// g_vw: per 64-key tile: word[(j>>3)*4+(j&3)][2*d+e]      (j=key-pair,  e=(j>>2)&1)
__device__ uint32_t g_qw[(size_t)BHc * Sc * 32];
__device__ uint32_t g_kw[(size_t)BHc * Sc * 32];
__device__ uint32_t g_vw[(size_t)BHc * Sc * 32];
__device__ float g_attn[(size_t)BSc * DMc];
__device__ float g_res[(size_t)BSc * DMc];

// ---------------------------------------------------------------------------
// helpers
// ---------------------------------------------------------------------------
__device__ __forceinline__ float ex2f(float x) {
    float r;
    asm("ex2.approx.ftz.f32 %0, %1;" : "=f"(r) : "f"(x));
    return r;
}

__device__ __forceinline__ uint32_t packbf(float lo, float hi) {
    uint32_t r;
    asm("cvt.rn.bf16x2.f32 %0, %1, %2;" : "=r"(r) : "f"(hi), "f"(lo));
    return r;
}

// bf16 m16n8k16
__device__ __forceinline__ void mma16(float c[4],
    uint32_t a0, uint32_t a1, uint32_t a2, uint32_t a3,
    uint32_t b0, uint32_t b1)
{
    asm volatile(
        "mma.sync.aligned.m16n8k16.row.col.f32.bf16.bf16.f32 "
        "{%0,%1,%2,%3},{%4,%5,%6,%7},{%8,%9},{%0,%1,%2,%3};"
        : "+f"(c[0]), "+f"(c[1]), "+f"(c[2]), "+f"(c[3])
        : "r"(a0), "r"(a1), "r"(a2), "r"(a3), "r"(b0), "r"(b1));
}

__device__ __forceinline__ void cp16(void* dst_smem, const void* src) {
    uint32_t d = (uint32_t)__cvta_generic_to_shared(dst_smem);
    asm volatile("cp.async.ca.shared.global [%0], [%1], 16;\n" :: "r"(d), "l"(src));
}
__device__ __forceinline__ void cp_commit() {
    asm volatile("cp.async.commit_group;\n");
}
template<int N> __device__ __forceinline__ void cp_wait() {
    asm volatile("cp.async.wait_group %0;\n" :: "n"(N));
}

// pair-permuted word position for k-pair index kp (0..15)
__device__ __forceinline__ int ppw(int kp) {
    return ((kp >> 3) << 3) + ((kp & 3) << 1) + ((kp >> 2) & 1);
}

// ---------------------------------------------------------------------------
// bf16 GEMM: C[m][n] = sum_k A[m][k] * W[n][k] (+bias) (+RoPE / +resid)
// Tile 128x64, Kc=32, 8 warps, double-buffered packed bf16x2 smem.
// All fragment loads are conflict-free LDS.64 (pair-permuted, stride 24).
// mode: 0=q(rope,*log2e/64,bf16) 1=k(rope,bf16 tile layout)
//       2=v(bias,bf16 tile layout) 3=out(residual -> g_res, fp32)
// ---------------------------------------------------------------------------
constexpr int GXW = 24;                 // packed words per row (16 used + pad)
constexpr int GX_SZ = 128 * GXW;        // X buffer words
constexpr int GW_SZ = 64 * GXW;

__global__ __launch_bounds__(256) void gemm_mma(
    const float* __restrict__ A, const float* __restrict__ W,
    const float* __restrict__ bias,
    const float* __restrict__ cosb, const float* __restrict__ sinb,
    const float* __restrict__ resid, int mode)
{
    extern __shared__ uint32_t gsh[];
    uint32_t* Xs[2] = { gsh,                    gsh + GX_SZ + GW_SZ };
    uint32_t* Ws[2] = { gsh + GX_SZ,            gsh + 2 * GX_SZ + GW_SZ };

    const int tid  = threadIdx.x;
    const int lane = tid & 31, wrp = tid >> 5;
    const int g = lane >> 2, q = lane & 3;
    const int m0 = blockIdx.y * 128, n0 = blockIdx.x * 64;

    const float* Ap = (mode == 3) ? g_attn : A;

    const int tr  = tid >> 3;               // 0..31
    const int lc4 = (tid & 7) * 4;          // float index 0..28
    const int pp0 = ppw(lc4 >> 1);          // word slot of k-pair lc4/2
    const int pp1 = ppw((lc4 >> 1) + 1);

    float4 xr[4], wr[2];
    #pragma unroll
    for (int p = 0; p < 4; p++)
        xr[p] = *(const float4*)&Ap[(size_t)(m0 + p * 32 + tr) * DMc + lc4];
    #pragma unroll
    for (int p = 0; p < 2; p++)
        wr[p] = *(const float4*)&W[(size_t)(n0 + p * 32 + tr) * DMc + lc4];

    float c[8][4] = {};
    int buf = 0;

    for (int k0 = 0; k0 < DMc; k0 += 32) {
        uint32_t* Xb = Xs[buf];
        uint32_t* Wb = Ws[buf];
        #pragma unroll
        for (int p = 0; p < 4; p++) {
            int r = (p * 32 + tr) * GXW;
            Xb[r + pp0] = packbf(xr[p].x, xr[p].y);
            Xb[r + pp1] = packbf(xr[p].z, xr[p].w);
        }
        #pragma unroll
        for (int p = 0; p < 2; p++) {
            int r = (p * 32 + tr) * GXW;
            Wb[r + pp0] = packbf(wr[p].x, wr[p].y);
            Wb[r + pp1] = packbf(wr[p].z, wr[p].w);
        }
        __syncthreads();

        if (k0 + 32 < DMc) {
            #pragma unroll
            for (int p = 0; p < 4; p++)
                xr[p] = *(const float4*)&Ap[(size_t)(m0 + p * 32 + tr) * DMc + k0 + 32 + lc4];
            #pragma unroll
            for (int p = 0; p < 2; p++)
                wr[p] = *(const float4*)&W[(size_t)(n0 + p * 32 + tr) * DMc + k0 + 32 + lc4];
        }

        #pragma unroll
        for (int st = 0; st < 2; st++) {
            uint2 aLo = *(uint2*)&Xb[(wrp * 16 + g    ) * GXW + st * 8 + 2 * q];
            uint2 aHi = *(uint2*)&Xb[(wrp * 16 + g + 8) * GXW + st * 8 + 2 * q];
            #pragma unroll
            for (int nt = 0; nt < 8; nt++) {
                uint2 b = *(uint2*)&Wb[(nt * 8 + g) * GXW + st * 8 + 2 * q];
                mma16(c[nt], aLo.x, aHi.x, aLo.y, aHi.y, b.x, b.y);
            }
        }
        buf ^= 1;
    }

    // ---- epilogue ----
    if (mode <= 1) {
        const int h = blockIdx.x;
        const float post = (mode == 0) ? (1.4426950408889634f / 64.0f) : 1.0f;
        #pragma unroll
        for (int rr = 0; rr < 2; rr++) {
            int row = m0 + wrp * 16 + g + rr * 8;
            int bb = row >> 12, sg = row & (Sc - 1);
            size_t hb = (size_t)(bb * Hc + h) * Sc * 32;
            #pragma unroll
            for (int nt = 0; nt < 4; nt++) {
                int d = nt * 8 + q * 2;      // [0,32), even
                float lo0 = c[nt][rr * 2 + 0]     + bias[n0 + d];
                float lo1 = c[nt][rr * 2 + 1]     + bias[n0 + d + 1];
                float hi0 = c[nt + 4][rr * 2 + 0] + bias[n0 + d + 32];
                float hi1 = c[nt + 4][rr * 2 + 1] + bias[n0 + d + 33];
                float c0 = cosb[sg * HDc + d],     c1 = cosb[sg * HDc + d + 1];
                float s0 = sinb[sg * HDc + d],     s1 = sinb[sg * HDc + d + 1];
                float r0 = (lo0 * c0 - hi0 * s0) * post;
                float r1 = (lo1 * c1 - hi1 * s1) * post;
                float r2 = (hi0 * c0 + lo0 * s0) * post;
                float r3 = (hi1 * c1 + lo1 * s1) * post;
                if (mode == 0) {
                    size_t base = hb + (size_t)sg * 32;
                    g_qw[base + nt * 4 + q]      = packbf(r0, r1);
                    g_qw[base + nt * 4 + q + 16] = packbf(r2, r3);
                } else {
                    int tile = sg >> 6, n = sg & 63;
                    size_t tb = hb + (size_t)tile * 2048;
                    int dp = nt * 4 + q;             // d/2 in [0,16)
                    int rrow = (dp >> 3) * 4 + (dp & 3);
                    int e = (dp >> 2) & 1;
                    g_kw[tb + rrow * 128 + 2 * n + e]        = packbf(r0, r1);
                    g_kw[tb + (rrow + 8) * 128 + 2 * n + e]  = packbf(r2, r3);  // dp+16
                }
            }
        }
    } else if (mode == 2) {
        const int h = blockIdx.x;
        #pragma unroll
        for (int rr = 0; rr < 2; rr++) {
            int row = m0 + wrp * 16 + g + rr * 8;
            int bb = row >> 12, sg = row & (Sc - 1);
            size_t hb = (size_t)(bb * Hc + h) * Sc * 32;
            int tile = sg >> 6;
            int jj = (sg >> 1) & 31;
            int rrow = (jj >> 3) * 4 + (jj & 3);
            int e = (jj >> 2) & 1;
            size_t bw = hb + (size_t)tile * 2048 + rrow * 128 + e;
            #pragma unroll
            for (int nt = 0; nt < 8; nt++) {
                int d = nt * 8 + q * 2;
                float v0 = c[nt][rr * 2 + 0] + bias[n0 + d];
                float v1 = c[nt][rr * 2 + 1] + bias[n0 + d + 1];
                float w0 = __shfl_down_sync(0xffffffffu, v0, 4);
                float w1 = __shfl_down_sync(0xffffffffu, v1, 4);
                if ((g & 1) == 0) {       // my key even -> low half; partner -> high
                    g_vw[bw + 2 * d]       = packbf(v0, w0);
                    g_vw[bw + 2 * (d + 1)] = packbf(v1, w1);
                }
            }
        }
    } else {
        #pragma unroll
        for (int rr = 0; rr < 2; rr++) {
            int row = m0 + wrp * 16 + g + rr * 8;
            #pragma unroll
            for (int nt = 0; nt < 8; nt++) {
                int col = n0 + nt * 8 + q * 2;
                float2 r = *(const float2*)&resid[(size_t)row * DMc + col];
                *(float2*)&g_res[(size_t)row * DMc + col] =
                    make_float2(c[nt][rr * 2 + 0] + r.x, c[nt][rr * 2 + 1] + r.y);
            }
        }
    }
}

// ---------------------------------------------------------------------------
// bf16 flash attention. BM=128, BN=64. Grid (S/128, B*H), 256 threads.
// (unchanged from R8: 312 us, regs 121, 2 CTAs/SM)
// ---------------------------------------------------------------------------
constexpr int TSTRIDE = 136;
constexpr int TSZ = 16 * TSTRIDE;   // 2176 words per tile

__device__ __forceinline__ void ldt(const uint32_t* src_tile, uint32_t* dst, int tid) {
    #pragma unroll
    for (int p = 0; p < 2; p++) {
        int f = p * 256 + tid;            // 0..511
        int r = f >> 5, w4 = (f & 31) * 4;
        cp16(&dst[r * TSTRIDE + w4], &src_tile[f * 4]);
    }
}

__global__ __launch_bounds__(256, 2) void flash_mma()
{
    __shared__ uint32_t sh[4 * TSZ];
    uint32_t* K0 = sh;
    uint32_t* K1 = sh + TSZ;
    uint32_t* V0 = sh + 2 * TSZ;
    uint32_t* V1 = sh + 3 * TSZ;

    const int tid  = threadIdx.x;
    const int lane = tid & 31, wrp = tid >> 5;
    const int g = lane >> 2, q = lane & 3;
    const int bh = blockIdx.y, m0 = blockIdx.x * 128;

    const uint32_t* qw = g_qw + (size_t)bh * Sc * 32;
    const uint32_t* kw = g_kw + (size_t)bh * Sc * 32;
    const uint32_t* vw = g_vw + (size_t)bh * Sc * 32;

    ldt(kw, K0, tid);
    ldt(vw, V0, tid);
    cp_commit();
    ldt(kw + 2048, K1, tid);
    ldt(vw + 2048, V1, tid);
    cp_commit();

    // Q fragments (bf16x2 packed) — loop-invariant
    uint32_t qa[4][4];
    {
        const uint32_t* q0 = qw + (size_t)(m0 + wrp * 16 + g) * 32;
        const uint32_t* q1 = q0 + 8 * 32;
        #pragma unroll
        for (int ks = 0; ks < 4; ks++) {
            qa[ks][0] = q0[8 * ks + q];
            qa[ks][1] = q1[8 * ks + q];
            qa[ks][2] = q0[8 * ks + q + 4];
            qa[ks][3] = q1[8 * ks + q + 4];
        }
    }

    cp_wait<1>();
    __syncthreads();

    float o[8][4] = {};
    float ps0 = 0.f, ps1 = 0.f;

    #pragma unroll 1
    for (int t = 0; t < Sc / 64; t++) {
        uint32_t* Ks = (t & 1) ? K1 : K0;
        uint32_t* Vs = (t & 1) ? V1 : V0;

        // S = Q K^T
        float s[8][4] = {};
        #pragma unroll
        for (int ks = 0; ks < 4; ks++) {
            #pragma unroll
            for (int nt = 0; nt < 8; nt++) {
                uint2 b = *(uint2*)&Ks[(ks * 4 + q) * TSTRIDE + 2 * (nt * 8 + g)];
                mma16(s[nt], qa[ks][0], qa[ks][1], qa[ks][2], qa[ks][3], b.x, b.y);
            }
        }

        // exp2 (log2e folded in q) + partial sums + bf16 pack (P-as-A frags)
        uint32_t pk[8][2];
        #pragma unroll
        for (int nt = 0; nt < 8; nt++) {
            float e0 = ex2f(s[nt][0]);
            float e1 = ex2f(s[nt][1]);
            float e2 = ex2f(s[nt][2]);
            float e3 = ex2f(s[nt][3]);
            ps0 += e0 + e1;
            ps1 += e2 + e3;
            pk[nt][0] = packbf(e0, e1);   // row g,   cols 2q,2q+1
            pk[nt][1] = packbf(e2, e3);   // row g+8
        }

        // O += P V
        #pragma unroll
        for (int ks = 0; ks < 4; ks++) {
            #pragma unroll
            for (int nt = 0; nt < 8; nt++) {
                uint2 b = *(uint2*)&Vs[(ks * 4 + q) * TSTRIDE + 2 * (nt * 8 + g)];
                mma16(o[nt], pk[2 * ks][0], pk[2 * ks][1],
                             pk[2 * ks + 1][0], pk[2 * ks + 1][1], b.x, b.y);
            }
        }

        if (t == Sc / 64 - 1) break;
        __syncthreads();
        if (t + 2 < Sc / 64) {
            uint32_t* Kd = (t & 1) ? K1 : K0;
            uint32_t* Vd = (t & 1) ? V1 : V0;
            ldt(kw + (size_t)(t + 2) * 2048, Kd, tid);
            ldt(vw + (size_t)(t + 2) * 2048, Vd, tid);
            cp_commit();
            cp_wait<1>();
        } else {
            cp_wait<0>();
        }
        __syncthreads();
    }

    // softmax denominators (4 lanes per row)
    ps0 += __shfl_xor_sync(0xffffffffu, ps0, 1);
    ps0 += __shfl_xor_sync(0xffffffffu, ps0, 2);
    ps1 += __shfl_xor_sync(0xffffffffu, ps1, 1);
    ps1 += __shfl_xor_sync(0xffffffffu, ps1, 2);
    float inv0 = 1.0f / ps0, inv1 = 1.0f / ps1;

    const int b = bh / Hc, h = bh % Hc;
    #pragma unroll
    for (int rr = 0; rr < 2; rr++) {
        int row = m0 + wrp * 16 + g + rr * 8;
        float inv = rr ? inv1 : inv0;
        size_t base = ((size_t)(b * Sc + row)) * DMc + h * HDc;
        #pragma unroll
        for (int nt = 0; nt < 8; nt++) {
            *(float2*)&g_attn[base + nt * 8 + q * 2] =
                make_float2(o[nt][rr * 2] * inv, o[nt][rr * 2 + 1] * inv);
        }
    }
}

// ---------------------------------------------------------------------------
// LayerNorm: one block per row of 768
// ---------------------------------------------------------------------------
__global__ __launch_bounds__(256) void ln_kernel(
    const float* __restrict__ gam, const float* __restrict__ bet,
    float* __restrict__ out)
{
    const int row = blockIdx.x;
    const int tid = threadIdx.x;
    const float* x = g_res + (size_t)row * DMc;

    float v0 = x[tid], v1 = x[tid + 256], v2 = x[tid + 512];
    float s  = v0 + v1 + v2;
    float sq = v0 * v0 + v1 * v1 + v2 * v2;

    #pragma unroll
    for (int off = 16; off >= 1; off >>= 1) {
        s  += __shfl_xor_sync(0xffffffffu, s,  off);
        sq += __shfl_xor_sync(0xffffffffu, sq, off);
    }

    __shared__ float ws[8], wq[8];
    int w = tid >> 5, lane = tid & 31;
    if (lane == 0) { ws[w] = s; wq[w] = sq; }
    __syncthreads();
    s = 0.f; sq = 0.f;
    #pragma unroll
    for (int i = 0; i < 8; i++) { s += ws[i]; sq += wq[i]; }

    const float inv_n = 1.0f / 768.0f;
    float mu  = s * inv_n;
    float var = sq * inv_n - mu * mu;
    float inv = rsqrtf(var + 1e-12f);

    float* op = out + (size_t)row * DMc;
    op[tid]       = (v0 - mu) * inv * gam[tid]       + bet[tid];
    op[tid + 256] = (v1 - mu) * inv * gam[tid + 256] + bet[tid + 256];
    op[tid + 512] = (v2 - mu) * inv * gam[tid + 512] + bet[tid + 512];
}

// ---------------------------------------------------------------------------
extern "C" void kernel_launch(void* const* d_in, const int* in_sizes, int n_in,
                              void* d_out, int out_size)
{
    const float* hidden = (const float*)d_in[0];
    const float* cosb   = (const float*)d_in[1];
    const float* sinb   = (const float*)d_in[2];
    const float* Wq     = (const float*)d_in[3];
    const float* bq     = (const float*)d_in[4];
    const float* Wk     = (const float*)d_in[5];
    const float* bk     = (const float*)d_in[6];
    const float* Wv     = (const float*)d_in[7];
    const float* bv     = (const float*)d_in[8];
    const float* Wo     = (const float*)d_in[9];
    const float* lng    = (const float*)d_in[10];
    const float* lnb    = (const float*)d_in[11];
    float* out = (float*)d_out;

    dim3 gg(DMc / 64, BSc / 128);   // (12, 64)
    const int gemm_smem = 2 * (GX_SZ + GW_SZ) * (int)sizeof(uint32_t);  // 36864
    cudaFuncSetAttribute(gemm_mma,
                         cudaFuncAttributeMaxDynamicSharedMemorySize, gemm_smem);

    gemm_mma<<<gg, 256, gemm_smem>>>(hidden, Wq, bq, cosb, sinb, nullptr, 0);
    gemm_mma<<<gg, 256, gemm_smem>>>(hidden, Wk, bk, cosb, sinb, nullptr, 1);
    gemm_mma<<<gg, 256, gemm_smem>>>(hidden, Wv, bv, cosb, sinb, nullptr, 2);

    flash_mma<<<dim3(Sc / 128, BHc), 256>>>();

    gemm_mma<<<gg, 256, gemm_smem>>>(hidden, Wo, nullptr, cosb, sinb, hidden, 3);
    ln_kernel<<<BSc, 256>>>(lng, lnb, out);
}

// round 14
// speedup vs baseline: 2.8097x; 1.0491x over previous
#include <cuda_runtime.h>
#include <cstdint>

constexpr int Bc  = 2;
constexpr int Sc  = 4096;
constexpr int DMc = 768;
constexpr int Hc  = 12;
constexpr int HDc = 64;
constexpr int BSc = Bc * Sc;
constexpr int BHc = Bc * Hc;

// Scratch (all bf16 packed as uint32 bf16x2 words unless noted)
// g_qw: [bh][s][d/2] natural, q pre-scaled by log2(e)/64
// g_kw/g_vw: per-64-key tile layouts (see R8) for flash cp.async
// g_xw/g_ww/g_aw: GEMM operands, [row][chunk(24)][16 words], pair-permuted
// g_res: fp32 pre-LN output
__device__ uint32_t g_qw[(size_t)BHc * Sc * 32];
__device__ uint32_t g_kw[(size_t)BHc * Sc * 32];
__device__ uint32_t g_vw[(size_t)BHc * Sc * 32];
__device__ uint32_t g_xw[(size_t)BSc * 384];
__device__ uint32_t g_ww[(size_t)4 * DMc * 384];
__device__ uint32_t g_aw[(size_t)BSc * 384];
__device__ float g_res[(size_t)BSc * DMc];

// ---------------------------------------------------------------------------
// helpers
// ---------------------------------------------------------------------------
__device__ __forceinline__ float ex2f(float x) {
    float r;
    asm("ex2.approx.ftz.f32 %0, %1;" : "=f"(r) : "f"(x));
    return r;
}

__device__ __forceinline__ uint32_t packbf(float lo, float hi) {
    uint32_t r;
    asm("cvt.rn.bf16x2.f32 %0, %1, %2;" : "=r"(r) : "f"(hi), "f"(lo));
    return r;
}

__device__ __forceinline__ void mma16(float c[4],
    uint32_t a0, uint32_t a1, uint32_t a2, uint32_t a3,
    uint32_t b0, uint32_t b1)
{
    asm volatile(
        "mma.sync.aligned.m16n8k16.row.col.f32.bf16.bf16.f32 "
        "{%0,%1,%2,%3},{%4,%5,%6,%7},{%8,%9},{%0,%1,%2,%3};"
        : "+f"(c[0]), "+f"(c[1]), "+f"(c[2]), "+f"(c[3])
        : "r"(a0), "r"(a1), "r"(a2), "r"(a3), "r"(b0), "r"(b1));
}

__device__ __forceinline__ void cp16(void* dst_smem, const void* src) {
    uint32_t d = (uint32_t)__cvta_generic_to_shared(dst_smem);
    asm volatile("cp.async.ca.shared.global [%0], [%1], 16;\n" :: "r"(d), "l"(src));
}
__device__ __forceinline__ void cp_commit() {
    asm volatile("cp.async.commit_group;\n");
}
template<int N> __device__ __forceinline__ void cp_wait() {
    asm volatile("cp.async.wait_group %0;\n" :: "n"(N));
}

// pair-permuted word slot for k-pair index kp (0..15)
__device__ __forceinline__ int ppw(int kp) {
    return ((kp >> 3) << 3) + ((kp & 3) << 1) + ((kp >> 2) & 1);
}

// ---------------------------------------------------------------------------
// Prepack: fp32 [nrows][768] -> bf16x2 [nrows][24][16] pair-permuted
// ---------------------------------------------------------------------------
__global__ __launch_bounds__(256) void pack_bf(
    const float* __restrict__ src, uint32_t* __restrict__ dst, int nrows)
{
    int idx = blockIdx.x * 256 + threadIdx.x;   // one float4 each
    if (idx >= nrows * 192) return;
    int row = idx / 192, fj = idx % 192;
    int chunk = fj >> 3, f = fj & 7;
    float4 v = *(const float4*)&src[(size_t)row * DMc + fj * 4];
    uint32_t* d = &dst[((size_t)row * 24 + chunk) * 16];
    d[ppw(2 * f)]     = packbf(v.x, v.y);
    d[ppw(2 * f + 1)] = packbf(v.z, v.w);
}

// ---------------------------------------------------------------------------
// bf16 GEMM: C[m][n] = sum_k A[m][k] * W[n][k] (+bias) (+RoPE / +resid)
// Tile 128x64, chunk=32, 8 warps. Operands pre-packed in gmem; staging is
// pure cp.async into a 4-buffer pipeline (depth 3), one barrier per iter.
// mode: 0=q(rope,*log2e/64) 1=k(rope, tile layout) 2=v(bias, tile layout)
//       3=out(residual -> g_res, fp32)
// ---------------------------------------------------------------------------
constexpr int GXW  = 24;              // smem row stride (16 used + 8 pad)
constexpr int XBUF = 128 * GXW;       // 3072 words
constexpr int WBUF = 64 * GXW;        // 1536 words
constexpr int GBUF = XBUF + WBUF;     // 4608 words per stage

__device__ __forceinline__ void g_stage(
    const uint32_t* __restrict__ Aw, const uint32_t* __restrict__ Ww,
    uint32_t* buf, int m0, int n0, int c, int tid)
{
    #pragma unroll
    for (int p = 0; p < 2; p++) {
        int f = p * 256 + tid;
        int row = f >> 2, w4 = (f & 3) * 4;
        cp16(&buf[row * GXW + w4], &Aw[((size_t)(m0 + row) * 24 + c) * 16 + w4]);
    }
    int row = tid >> 2, w4 = (tid & 3) * 4;
    cp16(&buf[XBUF + row * GXW + w4], &Ww[((size_t)(n0 + row) * 24 + c) * 16 + w4]);
}

__global__ __launch_bounds__(256) void gemm_mma(
    const uint32_t* __restrict__ Aw, const uint32_t* __restrict__ Ww,
    const float* __restrict__ bias,
    const float* __restrict__ cosb, const float* __restrict__ sinb,
    const float* __restrict__ resid, int mode)
{
    extern __shared__ uint32_t gsh[];

    const int tid  = threadIdx.x;
    const int lane = tid & 31, wrp = tid >> 5;
    const int g = lane >> 2, q = lane & 3;
    const int m0 = blockIdx.y * 128, n0 = blockIdx.x * 64;

    g_stage(Aw, Ww, gsh,            m0, n0, 0, tid); cp_commit();
    g_stage(Aw, Ww, gsh + GBUF,     m0, n0, 1, tid); cp_commit();
    g_stage(Aw, Ww, gsh + 2 * GBUF, m0, n0, 2, tid); cp_commit();

    float c[8][4] = {};

    for (int ch = 0; ch < 24; ch++) {
        cp_wait<2>();
        __syncthreads();
        if (ch + 3 < 24)
            g_stage(Aw, Ww, gsh + ((ch + 3) & 3) * GBUF, m0, n0, ch + 3, tid);
        cp_commit();

        uint32_t* Xb = gsh + (ch & 3) * GBUF;
        uint32_t* Wb = Xb + XBUF;
        #pragma unroll
        for (int st = 0; st < 2; st++) {
            uint2 aLo = *(uint2*)&Xb[(wrp * 16 + g    ) * GXW + st * 8 + 2 * q];
            uint2 aHi = *(uint2*)&Xb[(wrp * 16 + g + 8) * GXW + st * 8 + 2 * q];
            #pragma unroll
            for (int nt = 0; nt < 8; nt++) {
                uint2 b = *(uint2*)&Wb[(nt * 8 + g) * GXW + st * 8 + 2 * q];
                mma16(c[nt], aLo.x, aHi.x, aLo.y, aHi.y, b.x, b.y);
            }
        }
    }

    // ---- epilogue ----
    if (mode <= 1) {
        const int h = blockIdx.x;
        const float post = (mode == 0) ? (1.4426950408889634f / 64.0f) : 1.0f;
        #pragma unroll
        for (int rr = 0; rr < 2; rr++) {
            int row = m0 + wrp * 16 + g + rr * 8;
            int bb = row >> 12, sg = row & (Sc - 1);
            size_t hb = (size_t)(bb * Hc + h) * Sc * 32;
            #pragma unroll
            for (int nt = 0; nt < 4; nt++) {
                int d = nt * 8 + q * 2;      // [0,32), even
                float lo0 = c[nt][rr * 2 + 0]     + bias[n0 + d];
                float lo1 = c[nt][rr * 2 + 1]     + bias[n0 + d + 1];
                float hi0 = c[nt + 4][rr * 2 + 0] + bias[n0 + d + 32];
                float hi1 = c[nt + 4][rr * 2 + 1] + bias[n0 + d + 33];
                float c0 = cosb[sg * HDc + d],     c1 = cosb[sg * HDc + d + 1];
                float s0 = sinb[sg * HDc + d],     s1 = sinb[sg * HDc + d + 1];
                float r0 = (lo0 * c0 - hi0 * s0) * post;
                float r1 = (lo1 * c1 - hi1 * s1) * post;
                float r2 = (hi0 * c0 + lo0 * s0) * post;
                float r3 = (hi1 * c1 + lo1 * s1) * post;
                if (mode == 0) {
                    size_t base = hb + (size_t)sg * 32;
                    g_qw[base + nt * 4 + q]      = packbf(r0, r1);
                    g_qw[base + nt * 4 + q + 16] = packbf(r2, r3);
                } else {
                    int tile = sg >> 6, n = sg & 63;
                    size_t tb = hb + (size_t)tile * 2048;
                    int dp = nt * 4 + q;             // d/2 in [0,16)
                    int rrow = (dp >> 3) * 4 + (dp & 3);
                    int e = (dp >> 2) & 1;
                    g_kw[tb + rrow * 128 + 2 * n + e]        = packbf(r0, r1);
                    g_kw[tb + (rrow + 8) * 128 + 2 * n + e]  = packbf(r2, r3);
                }
            }
        }
    } else if (mode == 2) {
        const int h = blockIdx.x;
        #pragma unroll
        for (int rr = 0; rr < 2; rr++) {
            int row = m0 + wrp * 16 + g + rr * 8;
            int bb = row >> 12, sg = row & (Sc - 1);
            size_t hb = (size_t)(bb * Hc + h) * Sc * 32;
            int tile = sg >> 6;
            int jj = (sg >> 1) & 31;
            int rrow = (jj >> 3) * 4 + (jj & 3);
            int e = (jj >> 2) & 1;
            size_t bw = hb + (size_t)tile * 2048 + rrow * 128 + e;
            #pragma unroll
            for (int nt = 0; nt < 8; nt++) {
                int d = nt * 8 + q * 2;
                float v0 = c[nt][rr * 2 + 0] + bias[n0 + d];
                float v1 = c[nt][rr * 2 + 1] + bias[n0 + d + 1];
                float w0 = __shfl_down_sync(0xffffffffu, v0, 4);
                float w1 = __shfl_down_sync(0xffffffffu, v1, 4);
                if ((g & 1) == 0) {
                    g_vw[bw + 2 * d]       = packbf(v0, w0);
                    g_vw[bw + 2 * (d + 1)] = packbf(v1, w1);
                }
            }
        }
    } else {
        #pragma unroll
        for (int rr = 0; rr < 2; rr++) {
            int row = m0 + wrp * 16 + g + rr * 8;
            #pragma unroll
            for (int nt = 0; nt < 8; nt++) {
                int col = n0 + nt * 8 + q * 2;
                float2 r = *(const float2*)&resid[(size_t)row * DMc + col];
                *(float2*)&g_res[(size_t)row * DMc + col] =
                    make_float2(c[nt][rr * 2 + 0] + r.x, c[nt][rr * 2 + 1] + r.y);
            }
        }
    }
}

// ---------------------------------------------------------------------------
// bf16 flash attention (unchanged mainloop from R8; epilogue writes packed
// pair-permuted attn into g_aw for the out-proj GEMM).
// ---------------------------------------------------------------------------
constexpr int TSTRIDE = 136;
constexpr int TSZ = 16 * TSTRIDE;

__device__ __forceinline__ void ldt(const uint32_t* src_tile, uint32_t* dst, int tid) {
    #pragma unroll
    for (int p = 0; p < 2; p++) {
        int f = p * 256 + tid;
        int r = f >> 5, w4 = (f & 31) * 4;
        cp16(&dst[r * TSTRIDE + w4], &src_tile[f * 4]);
    }
}

__global__ __launch_bounds__(256, 2) void flash_mma()
{
    __shared__ uint32_t sh[4 * TSZ];
    uint32_t* K0 = sh;
    uint32_t* K1 = sh + TSZ;
    uint32_t* V0 = sh + 2 * TSZ;
    uint32_t* V1 = sh + 3 * TSZ;

    const int tid  = threadIdx.x;
    const int lane = tid & 31, wrp = tid >> 5;
    const int g = lane >> 2, q = lane & 3;
    const int bh = blockIdx.y, m0 = blockIdx.x * 128;

    const uint32_t* qw = g_qw + (size_t)bh * Sc * 32;
    const uint32_t* kw = g_kw + (size_t)bh * Sc * 32;
    const uint32_t* vw = g_vw + (size_t)bh * Sc * 32;

    ldt(kw, K0, tid);
    ldt(vw, V0, tid);
    cp_commit();
    ldt(kw + 2048, K1, tid);
    ldt(vw + 2048, V1, tid);
    cp_commit();

    uint32_t qa[4][4];
    {
        const uint32_t* q0 = qw + (size_t)(m0 + wrp * 16 + g) * 32;
        const uint32_t* q1 = q0 + 8 * 32;
        #pragma unroll
        for (int ks = 0; ks < 4; ks++) {
            qa[ks][0] = q0[8 * ks + q];
            qa[ks][1] = q1[8 * ks + q];
            qa[ks][2] = q0[8 * ks + q + 4];
            qa[ks][3] = q1[8 * ks + q + 4];
        }
    }

    cp_wait<1>();
    __syncthreads();

    float o[8][4] = {};
    float ps0 = 0.f, ps1 = 0.f;

    #pragma unroll 1
    for (int t = 0; t < Sc / 64; t++) {
        uint32_t* Ks = (t & 1) ? K1 : K0;
        uint32_t* Vs = (t & 1) ? V1 : V0;

        float s[8][4] = {};
        #pragma unroll
        for (int ks = 0; ks < 4; ks++) {
            #pragma unroll
            for (int nt = 0; nt < 8; nt++) {
                uint2 b = *(uint2*)&Ks[(ks * 4 + q) * TSTRIDE + 2 * (nt * 8 + g)];
                mma16(s[nt], qa[ks][0], qa[ks][1], qa[ks][2], qa[ks][3], b.x, b.y);
            }
        }

        uint32_t pk[8][2];
        #pragma unroll
        for (int nt = 0; nt < 8; nt++) {
            float e0 = ex2f(s[nt][0]);
            float e1 = ex2f(s[nt][1]);
            float e2 = ex2f(s[nt][2]);
            float e3 = ex2f(s[nt][3]);
            ps0 += e0 + e1;
            ps1 += e2 + e3;
            pk[nt][0] = packbf(e0, e1);
            pk[nt][1] = packbf(e2, e3);
        }

        #pragma unroll
        for (int ks = 0; ks < 4; ks++) {
            #pragma unroll
            for (int nt = 0; nt < 8; nt++) {
                uint2 b = *(uint2*)&Vs[(ks * 4 + q) * TSTRIDE + 2 * (nt * 8 + g)];
                mma16(o[nt], pk[2 * ks][0], pk[2 * ks][1],
                             pk[2 * ks + 1][0], pk[2 * ks + 1][1], b.x, b.y);
            }
        }

        if (t == Sc / 64 - 1) break;
        __syncthreads();
        if (t + 2 < Sc / 64) {
            uint32_t* Kd = (t & 1) ? K1 : K0;
            uint32_t* Vd = (t & 1) ? V1 : V0;
            ldt(kw + (size_t)(t + 2) * 2048, Kd, tid);
            ldt(vw + (size_t)(t + 2) * 2048, Vd, tid);
            cp_commit();
            cp_wait<1>();
        } else {
            cp_wait<0>();
        }
        __syncthreads();
    }

    ps0 += __shfl_xor_sync(0xffffffffu, ps0, 1);
    ps0 += __shfl_xor_sync(0xffffffffu, ps0, 2);
    ps1 += __shfl_xor_sync(0xffffffffu, ps1, 1);
    ps1 += __shfl_xor_sync(0xffffffffu, ps1, 2);
    float inv0 = 1.0f / ps0, inv1 = 1.0f / ps1;

    // epilogue: write attn packed pair-permuted into g_aw
    const int b = bh / Hc, h = bh % Hc;
    #pragma unroll
    for (int rr = 0; rr < 2; rr++) {
        int row = m0 + wrp * 16 + g + rr * 8;
        float inv = rr ? inv1 : inv0;
        size_t rb = (size_t)(b * Sc + row) * 24;
        #pragma unroll
        for (int nt = 0; nt < 8; nt++) {
            int kp = h * 32 + nt * 4 + q;
            int chunk = kp >> 4, slot = ppw(kp & 15);
            g_aw[(rb + chunk) * 16 + slot] =
                packbf(o[nt][rr * 2] * inv, o[nt][rr * 2 + 1] * inv);
        }
    }
}

// ---------------------------------------------------------------------------
// LayerNorm: one block per row of 768
// ---------------------------------------------------------------------------
__global__ __launch_bounds__(256) void ln_kernel(
    const float* __restrict__ gam, const float* __restrict__ bet,
    float* __restrict__ out)
{
    const int row = blockIdx.x;
    const int tid = threadIdx.x;
    const float* x = g_res + (size_t)row * DMc;

    float v0 = x[tid], v1 = x[tid + 256], v2 = x[tid + 512];
    float s  = v0 + v1 + v2;
    float sq = v0 * v0 + v1 * v1 + v2 * v2;

    #pragma unroll
    for (int off = 16; off >= 1; off >>= 1) {
        s  += __shfl_xor_sync(0xffffffffu, s,  off);
        sq += __shfl_xor_sync(0xffffffffu, sq, off);
    }

    __shared__ float ws[8], wq[8];
    int w = tid >> 5, lane = tid & 31;
    if (lane == 0) { ws[w] = s; wq[w] = sq; }
    __syncthreads();
    s = 0.f; sq = 0.f;
    #pragma unroll
    for (int i = 0; i < 8; i++) { s += ws[i]; sq += wq[i]; }

    const float inv_n = 1.0f / 768.0f;
    float mu  = s * inv_n;
    float var = sq * inv_n - mu * mu;
    float inv = rsqrtf(var + 1e-12f);

    float* op = out + (size_t)row * DMc;
    op[tid]       = (v0 - mu) * inv * gam[tid]       + bet[tid];
    op[tid + 256] = (v1 - mu) * inv * gam[tid + 256] + bet[tid + 256];
    op[tid + 512] = (v2 - mu) * inv * gam[tid + 512] + bet[tid + 512];
}

// ---------------------------------------------------------------------------
extern "C" void kernel_launch(void* const* d_in, const int* in_sizes, int n_in,
                              void* d_out, int out_size)
{
    const float* hidden = (const float*)d_in[0];
    const float* cosb   = (const float*)d_in[1];
    const float* sinb   = (const float*)d_in[2];
    const float* Wq     = (const float*)d_in[3];
    const float* bq     = (const float*)d_in[4];
    const float* Wk     = (const float*)d_in[5];
    const float* bk     = (const float*)d_in[6];
    const float* Wv     = (const float*)d_in[7];
    const float* bv     = (const float*)d_in[8];
    const float* Wo     = (const float*)d_in[9];
    const float* lng    = (const float*)d_in[10];
    const float* lnb    = (const float*)d_in[11];
    float* out = (float*)d_out;

    uint32_t* xw = nullptr; uint32_t* ww = nullptr; uint32_t* aw = nullptr;
    cudaGetSymbolAddress((void**)&xw, g_xw);
    cudaGetSymbolAddress((void**)&ww, g_ww);
    cudaGetSymbolAddress((void**)&aw, g_aw);

    // prepack X + 4 weight matrices
    pack_bf<<<(BSc * 192 + 255) / 256, 256>>>(hidden, xw, BSc);
    pack_bf<<<(DMc * 192 + 255) / 256, 256>>>(Wq, ww + (size_t)0 * DMc * 384, DMc);
    pack_bf<<<(DMc * 192 + 255) / 256, 256>>>(Wk, ww + (size_t)1 * DMc * 384, DMc);
    pack_bf<<<(DMc * 192 + 255) / 256, 256>>>(Wv, ww + (size_t)2 * DMc * 384, DMc);
    pack_bf<<<(DMc * 192 + 255) / 256, 256>>>(Wo, ww + (size_t)3 * DMc * 384, DMc);

    dim3 gg(DMc / 64, BSc / 128);   // (12, 64)
    const int gemm_smem = 4 * GBUF * (int)sizeof(uint32_t);  // 73728
    cudaFuncSetAttribute(gemm_mma,
                         cudaFuncAttributeMaxDynamicSharedMemorySize, gemm_smem);

    gemm_mma<<<gg, 256, gemm_smem>>>(xw, ww + (size_t)0 * DMc * 384, bq, cosb, sinb, nullptr, 0);
    gemm_mma<<<gg, 256, gemm_smem>>>(xw, ww + (size_t)1 * DMc * 384, bk, cosb, sinb, nullptr, 1);
    gemm_mma<<<gg, 256, gemm_smem>>>(xw, ww + (size_t)2 * DMc * 384, bv, cosb, sinb, nullptr, 2);

    flash_mma<<<dim3(Sc / 128, BHc), 256>>>();

    gemm_mma<<<gg, 256, gemm_smem>>>(aw, ww + (size_t)3 * DMc * 384, nullptr, cosb, sinb, hidden, 3);
    ln_kernel<<<BSc, 256>>>(lng, lnb, out);
}

// round 15
// speedup vs baseline: 3.0945x; 1.1014x over previous
#include <cuda_runtime.h>
#include <cstdint>

constexpr int Bc  = 2;
constexpr int Sc  = 4096;
constexpr int DMc = 768;
constexpr int Hc  = 12;
constexpr int HDc = 64;
constexpr int BSc = Bc * Sc;
constexpr int BHc = Bc * Hc;

// Scratch (all bf16 packed as uint32 bf16x2 words unless noted)
__device__ uint32_t g_qw[(size_t)BHc * Sc * 32];
__device__ uint32_t g_kw[(size_t)BHc * Sc * 32];
__device__ uint32_t g_vw[(size_t)BHc * Sc * 32];
__device__ uint32_t g_xw[(size_t)BSc * 384];
__device__ uint32_t g_ww[(size_t)4 * DMc * 384];
__device__ uint32_t g_aw[(size_t)BSc * 384];
__device__ float g_res[(size_t)BSc * DMc];

// ---------------------------------------------------------------------------
// helpers
// ---------------------------------------------------------------------------
__device__ __forceinline__ float ex2f(float x) {
    float r;
    asm("ex2.approx.ftz.f32 %0, %1;" : "=f"(r) : "f"(x));
    return r;
}

__device__ __forceinline__ uint32_t packbf(float lo, float hi) {
    uint32_t r;
    asm("cvt.rn.bf16x2.f32 %0, %1, %2;" : "=r"(r) : "f"(hi), "f"(lo));
    return r;
}

__device__ __forceinline__ void mma16(float c[4],
    uint32_t a0, uint32_t a1, uint32_t a2, uint32_t a3,
    uint32_t b0, uint32_t b1)
{
    asm volatile(
        "mma.sync.aligned.m16n8k16.row.col.f32.bf16.bf16.f32 "
        "{%0,%1,%2,%3},{%4,%5,%6,%7},{%8,%9},{%0,%1,%2,%3};"
        : "+f"(c[0]), "+f"(c[1]), "+f"(c[2]), "+f"(c[3])
        : "r"(a0), "r"(a1), "r"(a2), "r"(a3), "r"(b0), "r"(b1));
}

__device__ __forceinline__ void cp16(void* dst_smem, const void* src) {
    uint32_t d = (uint32_t)__cvta_generic_to_shared(dst_smem);
    asm volatile("cp.async.ca.shared.global [%0], [%1], 16;\n" :: "r"(d), "l"(src));
}
__device__ __forceinline__ void cp_commit() {
    asm volatile("cp.async.commit_group;\n");
}
template<int N> __device__ __forceinline__ void cp_wait() {
    asm volatile("cp.async.wait_group %0;\n" :: "n"(N));
}

// pair-permuted word slot for k-pair index kp (0..15)
__device__ __forceinline__ int ppw(int kp) {
    return ((kp >> 3) << 3) + ((kp & 3) << 1) + ((kp >> 2) & 1);
}

// ---------------------------------------------------------------------------
// Prepack ALL operands in one launch:
// fp32 [rows][768] -> bf16x2 [rows][24][16] pair-permuted.
// block range: [0, BSc*192) = X; then 4 weight matrices of DMc*192 each.
// ---------------------------------------------------------------------------
__global__ __launch_bounds__(256) void pack_all(
    const float* __restrict__ hidden,
    const float* __restrict__ Wq, const float* __restrict__ Wk,
    const float* __restrict__ Wv, const float* __restrict__ Wo)
{
    int idx = blockIdx.x * 256 + threadIdx.x;
    const float* src;
    uint32_t* dst;
    int rel;
    if (idx < BSc * 192) {
        src = hidden; dst = g_xw; rel = idx;
    } else {
        int t = idx - BSc * 192;
        int which = t / (DMc * 192);
        rel = t % (DMc * 192);
        src = (which == 0) ? Wq : (which == 1) ? Wk : (which == 2) ? Wv : Wo;
        dst = g_ww + (size_t)which * DMc * 384;
    }
    int row = rel / 192, fj = rel % 192;
    int chunk = fj >> 3, f = fj & 7;
    float4 v = *(const float4*)&src[(size_t)row * DMc + fj * 4];
    uint32_t* d = &dst[((size_t)row * 24 + chunk) * 16];
    d[ppw(2 * f)]     = packbf(v.x, v.y);
    d[ppw(2 * f + 1)] = packbf(v.z, v.w);
}

// ---------------------------------------------------------------------------
// bf16 GEMM: C[m][n] = sum_k A[m][k] * W[n][k] (+bias) (+RoPE / +resid)
// Tile 128x128, chunk=32 floats, 8 warps: warp grid 4(m) x 2(n),
// warp tile 32 rows x 64 cols (one full head). c[2][8][4].
// 4-buffer cp.async pipeline, depth 3, one barrier/iter.
// mode: 0=q(rope,*log2e/64) 1=k(rope, tile layout) 2=v(bias, tile layout)
//       3=out(residual -> g_res, fp32)
// ---------------------------------------------------------------------------
constexpr int GXW  = 24;              // smem row stride (16 used + 8 pad)
constexpr int XBUF = 128 * GXW;       // 3072 words
constexpr int WBUF = 128 * GXW;       // 3072 words
constexpr int GBUF = XBUF + WBUF;     // 6144 words per stage (24 KB)

__device__ __forceinline__ void g_stage(
    const uint32_t* __restrict__ Aw, const uint32_t* __restrict__ Ww,
    uint32_t* buf, int m0, int n0, int c, int tid)
{
    #pragma unroll
    for (int p = 0; p < 2; p++) {
        int f = p * 256 + tid;
        int row = f >> 2, w4 = (f & 3) * 4;
        cp16(&buf[row * GXW + w4], &Aw[((size_t)(m0 + row) * 24 + c) * 16 + w4]);
    }
    #pragma unroll
    for (int p = 0; p < 2; p++) {
        int f = p * 256 + tid;
        int row = f >> 2, w4 = (f & 3) * 4;
        cp16(&buf[XBUF + row * GXW + w4],
             &Ww[((size_t)(n0 + row) * 24 + c) * 16 + w4]);
    }
}

__global__ __launch_bounds__(256) void gemm_mma(
    const uint32_t* __restrict__ Aw, const uint32_t* __restrict__ Ww,
    const float* __restrict__ bias,
    const float* __restrict__ cosb, const float* __restrict__ sinb,
    const float* __restrict__ resid, int mode)
{
    extern __shared__ uint32_t gsh[];

    const int tid  = threadIdx.x;
    const int lane = tid & 31, wrp = tid >> 5;
    const int g = lane >> 2, q = lane & 3;
    const int wm = wrp & 3, wn = wrp >> 2;      // warp grid 4 x 2
    const int m0 = blockIdx.y * 128, n0 = blockIdx.x * 128;

    g_stage(Aw, Ww, gsh,            m0, n0, 0, tid); cp_commit();
    g_stage(Aw, Ww, gsh + GBUF,     m0, n0, 1, tid); cp_commit();
    g_stage(Aw, Ww, gsh + 2 * GBUF, m0, n0, 2, tid); cp_commit();

    float c[2][8][4] = {};

    const int arow0 = (wm * 32 + g) * GXW;        // m-frag 0, row g
    const int brow0 = (wn * 64 + g) * GXW;

    for (int ch = 0; ch < 24; ch++) {
        cp_wait<2>();
        __syncthreads();
        if (ch + 3 < 24)
            g_stage(Aw, Ww, gsh + ((ch + 3) & 3) * GBUF, m0, n0, ch + 3, tid);
        cp_commit();

        uint32_t* Xb = gsh + (ch & 3) * GBUF;
        uint32_t* Wb = Xb + XBUF;
        #pragma unroll
        for (int st = 0; st < 2; st++) {
            int so = st * 8 + 2 * q;
            uint2 a0Lo = *(uint2*)&Xb[arow0 + so];
            uint2 a0Hi = *(uint2*)&Xb[arow0 + 8 * GXW + so];
            uint2 a1Lo = *(uint2*)&Xb[arow0 + 16 * GXW + so];
            uint2 a1Hi = *(uint2*)&Xb[arow0 + 24 * GXW + so];
            #pragma unroll
            for (int nt = 0; nt < 8; nt++) {
                uint2 b = *(uint2*)&Wb[brow0 + nt * 8 * GXW + so];
                mma16(c[0][nt], a0Lo.x, a0Hi.x, a0Lo.y, a0Hi.y, b.x, b.y);
                mma16(c[1][nt], a1Lo.x, a1Hi.x, a1Lo.y, a1Hi.y, b.x, b.y);
            }
        }
    }

    // ---- epilogue ----
    const int h = blockIdx.x * 2 + wn;            // head (modes 0-2)
    const int nb = n0 + wn * 64;                  // warp col base

    if (mode <= 1) {
        const float post = (mode == 0) ? (1.4426950408889634f / 64.0f) : 1.0f;
        #pragma unroll
        for (int mf = 0; mf < 2; mf++) {
            #pragma unroll
            for (int rr = 0; rr < 2; rr++) {
                int row = m0 + wm * 32 + mf * 16 + g + rr * 8;
                int bb = row >> 12, sg = row & (Sc - 1);
                size_t hb = (size_t)(bb * Hc + h) * Sc * 32;
                #pragma unroll
                for (int nt = 0; nt < 4; nt++) {
                    int d = nt * 8 + q * 2;      // [0,32), even
                    float lo0 = c[mf][nt][rr * 2 + 0]     + bias[nb + d];
                    float lo1 = c[mf][nt][rr * 2 + 1]     + bias[nb + d + 1];
                    float hi0 = c[mf][nt + 4][rr * 2 + 0] + bias[nb + d + 32];
                    float hi1 = c[mf][nt + 4][rr * 2 + 1] + bias[nb + d + 33];
                    float c0 = cosb[sg * HDc + d],     c1 = cosb[sg * HDc + d + 1];
                    float s0 = sinb[sg * HDc + d],     s1 = sinb[sg * HDc + d + 1];
                    float r0 = (lo0 * c0 - hi0 * s0) * post;
                    float r1 = (lo1 * c1 - hi1 * s1) * post;
                    float r2 = (hi0 * c0 + lo0 * s0) * post;
                    float r3 = (hi1 * c1 + lo1 * s1) * post;
                    if (mode == 0) {
                        size_t base = hb + (size_t)sg * 32;
                        g_qw[base + nt * 4 + q]      = packbf(r0, r1);
                        g_qw[base + nt * 4 + q + 16] = packbf(r2, r3);
                    } else {
                        int tile = sg >> 6, n = sg & 63;
                        size_t tb = hb + (size_t)tile * 2048;
                        int dp = nt * 4 + q;
                        int rrow = (dp >> 3) * 4 + (dp & 3);
                        int e = (dp >> 2) & 1;
                        g_kw[tb + rrow * 128 + 2 * n + e]       = packbf(r0, r1);
                        g_kw[tb + (rrow + 8) * 128 + 2 * n + e] = packbf(r2, r3);
                    }
                }
            }
        }
    } else if (mode == 2) {
        #pragma unroll
        for (int mf = 0; mf < 2; mf++) {
            #pragma unroll
            for (int rr = 0; rr < 2; rr++) {
                int row = m0 + wm * 32 + mf * 16 + g + rr * 8;
                int bb = row >> 12, sg = row & (Sc - 1);
                size_t hb = (size_t)(bb * Hc + h) * Sc * 32;
                int tile = sg >> 6;
                int jj = (sg >> 1) & 31;
                int rrow = (jj >> 3) * 4 + (jj & 3);
                int e = (jj >> 2) & 1;
                size_t bw = hb + (size_t)tile * 2048 + rrow * 128 + e;
                #pragma unroll
                for (int nt = 0; nt < 8; nt++) {
                    int d = nt * 8 + q * 2;
                    float v0 = c[mf][nt][rr * 2 + 0] + bias[nb + d];
                    float v1 = c[mf][nt][rr * 2 + 1] + bias[nb + d + 1];
                    float w0 = __shfl_down_sync(0xffffffffu, v0, 4);
                    float w1 = __shfl_down_sync(0xffffffffu, v1, 4);
                    if ((g & 1) == 0) {
                        g_vw[bw + 2 * d]       = packbf(v0, w0);
                        g_vw[bw + 2 * (d + 1)] = packbf(v1, w1);
                    }
                }
            }
        }
    } else {
        #pragma unroll
        for (int mf = 0; mf < 2; mf++) {
            #pragma unroll
            for (int rr = 0; rr < 2; rr++) {
                int row = m0 + wm * 32 + mf * 16 + g + rr * 8;
                #pragma unroll
                for (int nt = 0; nt < 8; nt++) {
                    int col = nb + nt * 8 + q * 2;
                    float2 r = *(const float2*)&resid[(size_t)row * DMc + col];
                    *(float2*)&g_res[(size_t)row * DMc + col] =
                        make_float2(c[mf][nt][rr * 2 + 0] + r.x,
                                    c[mf][nt][rr * 2 + 1] + r.y);
                }
            }
        }
    }
}

// ---------------------------------------------------------------------------
// bf16 flash attention (unchanged from R14; 311 us)
// ---------------------------------------------------------------------------
constexpr int TSTRIDE = 136;
constexpr int TSZ = 16 * TSTRIDE;

__device__ __forceinline__ void ldt(const uint32_t* src_tile, uint32_t* dst, int tid) {
    #pragma unroll
    for (int p = 0; p < 2; p++) {
        int f = p * 256 + tid;
        int r = f >> 5, w4 = (f & 31) * 4;
        cp16(&dst[r * TSTRIDE + w4], &src_tile[f * 4]);
    }
}

__global__ __launch_bounds__(256, 2) void flash_mma()
{
    __shared__ uint32_t sh[4 * TSZ];
    uint32_t* K0 = sh;
    uint32_t* K1 = sh + TSZ;
    uint32_t* V0 = sh + 2 * TSZ;
    uint32_t* V1 = sh + 3 * TSZ;

    const int tid  = threadIdx.x;
    const int lane = tid & 31, wrp = tid >> 5;
    const int g = lane >> 2, q = lane & 3;
    const int bh = blockIdx.y, m0 = blockIdx.x * 128;

    const uint32_t* qw = g_qw + (size_t)bh * Sc * 32;
    const uint32_t* kw = g_kw + (size_t)bh * Sc * 32;
    const uint32_t* vw = g_vw + (size_t)bh * Sc * 32;

    ldt(kw, K0, tid);
    ldt(vw, V0, tid);
    cp_commit();
    ldt(kw + 2048, K1, tid);
    ldt(vw + 2048, V1, tid);
    cp_commit();

    uint32_t qa[4][4];
    {
        const uint32_t* q0 = qw + (size_t)(m0 + wrp * 16 + g) * 32;
        const uint32_t* q1 = q0 + 8 * 32;
        #pragma unroll
        for (int ks = 0; ks < 4; ks++) {
            qa[ks][0] = q0[8 * ks + q];
            qa[ks][1] = q1[8 * ks + q];
            qa[ks][2] = q0[8 * ks + q + 4];
            qa[ks][3] = q1[8 * ks + q + 4];
        }
    }

    cp_wait<1>();
    __syncthreads();

    float o[8][4] = {};
    float ps0 = 0.f, ps1 = 0.f;

    #pragma unroll 1
    for (int t = 0; t < Sc / 64; t++) {
        uint32_t* Ks = (t & 1) ? K1 : K0;
        uint32_t* Vs = (t & 1) ? V1 : V0;

        float s[8][4] = {};
        #pragma unroll
        for (int ks = 0; ks < 4; ks++) {
            #pragma unroll
            for (int nt = 0; nt < 8; nt++) {
                uint2 b = *(uint2*)&Ks[(ks * 4 + q) * TSTRIDE + 2 * (nt * 8 + g)];
                mma16(s[nt], qa[ks][0], qa[ks][1], qa[ks][2], qa[ks][3], b.x, b.y);
            }
        }

        uint32_t pk[8][2];
        #pragma unroll
        for (int nt = 0; nt < 8; nt++) {
            float e0 = ex2f(s[nt][0]);
            float e1 = ex2f(s[nt][1]);
            float e2 = ex2f(s[nt][2]);
            float e3 = ex2f(s[nt][3]);
            ps0 += e0 + e1;
            ps1 += e2 + e3;
            pk[nt][0] = packbf(e0, e1);
            pk[nt][1] = packbf(e2, e3);
        }

        #pragma unroll
        for (int ks = 0; ks < 4; ks++) {
            #pragma unroll
            for (int nt = 0; nt < 8; nt++) {
                uint2 b = *(uint2*)&Vs[(ks * 4 + q) * TSTRIDE + 2 * (nt * 8 + g)];
                mma16(o[nt], pk[2 * ks][0], pk[2 * ks][1],
                             pk[2 * ks + 1][0], pk[2 * ks + 1][1], b.x, b.y);
            }
        }

        if (t == Sc / 64 - 1) break;
        __syncthreads();
        if (t + 2 < Sc / 64) {
            uint32_t* Kd = (t & 1) ? K1 : K0;
            uint32_t* Vd = (t & 1) ? V1 : V0;
            ldt(kw + (size_t)(t + 2) * 2048, Kd, tid);
            ldt(vw + (size_t)(t + 2) * 2048, Vd, tid);
            cp_commit();
            cp_wait<1>();
        } else {
            cp_wait<0>();
        }
        __syncthreads();
    }

    ps0 += __shfl_xor_sync(0xffffffffu, ps0, 1);
    ps0 += __shfl_xor_sync(0xffffffffu, ps0, 2);
    ps1 += __shfl_xor_sync(0xffffffffu, ps1, 1);
    ps1 += __shfl_xor_sync(0xffffffffu, ps1, 2);
    float inv0 = 1.0f / ps0, inv1 = 1.0f / ps1;

    const int b = bh / Hc, h = bh % Hc;
    #pragma unroll
    for (int rr = 0; rr < 2; rr++) {
        int row = m0 + wrp * 16 + g + rr * 8;
        float inv = rr ? inv1 : inv0;
        size_t rb = (size_t)(b * Sc + row) * 24;
        #pragma unroll
        for (int nt = 0; nt < 8; nt++) {
            int kp = h * 32 + nt * 4 + q;
            int chunk = kp >> 4, slot = ppw(kp & 15);
            g_aw[(rb + chunk) * 16 + slot] =
                packbf(o[nt][rr * 2] * inv, o[nt][rr * 2 + 1] * inv);
        }
    }
}

// ---------------------------------------------------------------------------
// LayerNorm: one WARP per row (no smem, no block barrier). 8 rows/block.
// ---------------------------------------------------------------------------
__global__ __launch_bounds__(256) void ln_kernel(
    const float* __restrict__ gam, const float* __restrict__ bet,
    float* __restrict__ out)
{
    const int wid = threadIdx.x >> 5, lane = threadIdx.x & 31;
    const int row = blockIdx.x * 8 + wid;
    const float* x = g_res + (size_t)row * DMc;

    float4 v[6];
    float s = 0.f, sq = 0.f;
    #pragma unroll
    for (int i = 0; i < 6; i++) {
        v[i] = *(const float4*)&x[(i * 32 + lane) * 4];
        s  += v[i].x + v[i].y + v[i].z + v[i].w;
        sq += v[i].x * v[i].x + v[i].y * v[i].y
            + v[i].z * v[i].z + v[i].w * v[i].w;
    }
    #pragma unroll
    for (int off = 16; off >= 1; off >>= 1) {
        s  += __shfl_xor_sync(0xffffffffu, s,  off);
        sq += __shfl_xor_sync(0xffffffffu, sq, off);
    }
    const float inv_n = 1.0f / 768.0f;
    float mu  = s * inv_n;
    float var = sq * inv_n - mu * mu;
    float inv = rsqrtf(var + 1e-12f);

    float* op = out + (size_t)row * DMc;
    #pragma unroll
    for (int i = 0; i < 6; i++) {
        int e = (i * 32 + lane) * 4;
        float4 gm = *(const float4*)&gam[e];
        float4 bt = *(const float4*)&bet[e];
        *(float4*)&op[e] = make_float4(
            (v[i].x - mu) * inv * gm.x + bt.x,
            (v[i].y - mu) * inv * gm.y + bt.y,
            (v[i].z - mu) * inv * gm.z + bt.z,
            (v[i].w - mu) * inv * gm.w + bt.w);
    }
}

// ---------------------------------------------------------------------------
extern "C" void kernel_launch(void* const* d_in, const int* in_sizes, int n_in,
                              void* d_out, int out_size)
{
    const float* hidden = (const float*)d_in[0];
    const float* cosb   = (const float*)d_in[1];
    const float* sinb   = (const float*)d_in[2];
    const float* Wq     = (const float*)d_in[3];
    const float* bq     = (const float*)d_in[4];
    const float* Wk     = (const float*)d_in[5];
    const float* bk     = (const float*)d_in[6];
    const float* Wv     = (const float*)d_in[7];
    const float* bv     = (const float*)d_in[8];
    const float* Wo     = (const float*)d_in[9];
    const float* lng    = (const float*)d_in[10];
    const float* lnb    = (const float*)d_in[11];
    float* out = (float*)d_out;

    uint32_t* xw = nullptr; uint32_t* ww = nullptr; uint32_t* aw = nullptr;
    cudaGetSymbolAddress((void**)&xw, g_xw);
    cudaGetSymbolAddress((void**)&ww, g_ww);
    cudaGetSymbolAddress((void**)&aw, g_aw);

    // prepack X + 4 weight matrices (single launch)
    const int pack_total = BSc * 192 + 4 * DMc * 192;
    pack_all<<<(pack_total + 255) / 256, 256>>>(hidden, Wq, Wk, Wv, Wo);

    dim3 gg(DMc / 128, BSc / 128);   // (6, 64)
    const int gemm_smem = 4 * GBUF * (int)sizeof(uint32_t);  // 98304
    cudaFuncSetAttribute(gemm_mma,
                         cudaFuncAttributeMaxDynamicSharedMemorySize, gemm_smem);

    gemm_mma<<<gg, 256, gemm_smem>>>(xw, ww + (size_t)0 * DMc * 384, bq, cosb, sinb, nullptr, 0);
    gemm_mma<<<gg, 256, gemm_smem>>>(xw, ww + (size_t)1 * DMc * 384, bk, cosb, sinb, nullptr, 1);
    gemm_mma<<<gg, 256, gemm_smem>>>(xw, ww + (size_t)2 * DMc * 384, bv, cosb, sinb, nullptr, 2);

    flash_mma<<<dim3(Sc / 128, BHc), 256>>>();

    gemm_mma<<<gg, 256, gemm_smem>>>(aw, ww + (size_t)3 * DMc * 384, nullptr, cosb, sinb, hidden, 3);
    ln_kernel<<<BSc / 8, 256>>>(lng, lnb, out);
}

// round 16
// speedup vs baseline: 3.3925x; 1.0963x over previous
#include <cuda_runtime.h>
#include <cstdint>

constexpr int Bc  = 2;
constexpr int Sc  = 4096;
constexpr int DMc = 768;
constexpr int Hc  = 12;
constexpr int HDc = 64;
constexpr int BSc = Bc * Sc;
constexpr int BHc = Bc * Hc;

// Scratch (all bf16 packed as uint32 bf16x2 words unless noted)
__device__ uint32_t g_qw[(size_t)BHc * Sc * 32];
__device__ uint32_t g_kw[(size_t)BHc * Sc * 32];
__device__ uint32_t g_vw[(size_t)BHc * Sc * 32];
__device__ uint32_t g_xw[(size_t)BSc * 384];
__device__ uint32_t g_ww[(size_t)4 * DMc * 384];
__device__ uint32_t g_aw[(size_t)BSc * 384];
__device__ float g_res[(size_t)BSc * DMc];

// ---------------------------------------------------------------------------
// helpers
// ---------------------------------------------------------------------------
__device__ __forceinline__ float ex2f(float x) {
    float r;
    asm("ex2.approx.ftz.f32 %0, %1;" : "=f"(r) : "f"(x));
    return r;
}

__device__ __forceinline__ uint32_t packbf(float lo, float hi) {
    uint32_t r;
    asm("cvt.rn.bf16x2.f32 %0, %1, %2;" : "=r"(r) : "f"(hi), "f"(lo));
    return r;
}

__device__ __forceinline__ void mma16(float c[4],
    uint32_t a0, uint32_t a1, uint32_t a2, uint32_t a3,
    uint32_t b0, uint32_t b1)
{
    asm volatile(
        "mma.sync.aligned.m16n8k16.row.col.f32.bf16.bf16.f32 "
        "{%0,%1,%2,%3},{%4,%5,%6,%7},{%8,%9},{%0,%1,%2,%3};"
        : "+f"(c[0]), "+f"(c[1]), "+f"(c[2]), "+f"(c[3])
        : "r"(a0), "r"(a1), "r"(a2), "r"(a3), "r"(b0), "r"(b1));
}

__device__ __forceinline__ void cp16(void* dst_smem, const void* src) {
    uint32_t d = (uint32_t)__cvta_generic_to_shared(dst_smem);
    asm volatile("cp.async.ca.shared.global [%0], [%1], 16;\n" :: "r"(d), "l"(src));
}
__device__ __forceinline__ void cp_commit() {
    asm volatile("cp.async.commit_group;\n");
}
template<int N> __device__ __forceinline__ void cp_wait() {
    asm volatile("cp.async.wait_group %0;\n" :: "n"(N));
}

// pair-permuted word slot for k-pair index kp (0..15)
__device__ __forceinline__ int ppw(int kp) {
    return ((kp >> 3) << 3) + ((kp & 3) << 1) + ((kp >> 2) & 1);
}

// ---------------------------------------------------------------------------
// Prepack ALL operands in one launch:
// fp32 [rows][768] -> bf16x2 [rows][24][16] pair-permuted.
// ---------------------------------------------------------------------------
__global__ __launch_bounds__(256) void pack_all(
    const float* __restrict__ hidden,
    const float* __restrict__ Wq, const float* __restrict__ Wk,
    const float* __restrict__ Wv, const float* __restrict__ Wo)
{
    int idx = blockIdx.x * 256 + threadIdx.x;
    const float* src;
    uint32_t* dst;
    int rel;
    if (idx < BSc * 192) {
        src = hidden; dst = g_xw; rel = idx;
    } else {
        int t = idx - BSc * 192;
        int which = t / (DMc * 192);
        rel = t % (DMc * 192);
        src = (which == 0) ? Wq : (which == 1) ? Wk : (which == 2) ? Wv : Wo;
        dst = g_ww + (size_t)which * DMc * 384;
    }
    int row = rel / 192, fj = rel % 192;
    int chunk = fj >> 3, f = fj & 7;
    float4 v = *(const float4*)&src[(size_t)row * DMc + fj * 4];
    uint32_t* d = &dst[((size_t)row * 24 + chunk) * 16];
    d[ppw(2 * f)]     = packbf(v.x, v.y);
    d[ppw(2 * f + 1)] = packbf(v.z, v.w);
}

// ---------------------------------------------------------------------------
// GEMM core: tile 128x128, 24 chunks, 8 warps (4m x 2n), c[2][8][4].
// Strength-reduced staging (running pointers, +16 words/chunk) and
// 6x4-unrolled mainloop so buffer bases are compile-time constants.
// ---------------------------------------------------------------------------
constexpr int GXW  = 24;
constexpr int XBUF = 128 * GXW;
constexpr int WBUF = 128 * GXW;
constexpr int GBUF = XBUF + WBUF;     // 6144 words / stage (24 KB)

struct StagePtrs {
    const uint32_t *a0, *a1, *w0, *w1;
    uint32_t dx0, dx1, dw0, dw1;      // smem word offsets within buffer
};

__device__ __forceinline__ void stage_chunk(StagePtrs& sp, uint32_t* buf) {
    cp16(buf + sp.dx0, sp.a0);
    cp16(buf + sp.dx1, sp.a1);
    cp16(buf + sp.dw0, sp.w0);
    cp16(buf + sp.dw1, sp.w1);
    sp.a0 += 16; sp.a1 += 16; sp.w0 += 16; sp.w1 += 16;
}

__device__ __forceinline__ void gemm_core(
    const uint32_t* __restrict__ Aw, const uint32_t* __restrict__ Ww,
    uint32_t* gsh, int m0, int n0, int tid,
    int arow0, int brow0, int q, float c[2][8][4])
{
    const int srow = tid >> 2, sw4 = (tid & 3) * 4;
    StagePtrs sp;
    sp.a0 = Aw + (size_t)(m0 + srow) * 384 + sw4;
    sp.a1 = sp.a0 + (size_t)64 * 384;
    sp.w0 = Ww + (size_t)(n0 + srow) * 384 + sw4;
    sp.w1 = sp.w0 + (size_t)64 * 384;
    sp.dx0 = srow * GXW + sw4;
    sp.dx1 = (srow + 64) * GXW + sw4;
    sp.dw0 = XBUF + srow * GXW + sw4;
    sp.dw1 = XBUF + (srow + 64) * GXW + sw4;

    stage_chunk(sp, gsh);            cp_commit();
    stage_chunk(sp, gsh + GBUF);     cp_commit();
    stage_chunk(sp, gsh + 2 * GBUF); cp_commit();

    const int so0 = 2 * q, so1 = 8 + 2 * q;

    for (int mc = 0; mc < 6; mc++) {
        #pragma unroll
        for (int u = 0; u < 4; u++) {
            const int ch = mc * 4 + u;
            cp_wait<2>();
            __syncthreads();
            if (ch < 21)
                stage_chunk(sp, gsh + ((u + 3) & 3) * GBUF);
            cp_commit();

            uint32_t* Xb = gsh + u * GBUF;
            uint32_t* Wb = Xb + XBUF;
            #pragma unroll
            for (int st = 0; st < 2; st++) {
                const int so = st ? so1 : so0;
                uint2 a0Lo = *(uint2*)&Xb[arow0 + so];
                uint2 a0Hi = *(uint2*)&Xb[arow0 + 8 * GXW + so];
                uint2 a1Lo = *(uint2*)&Xb[arow0 + 16 * GXW + so];
                uint2 a1Hi = *(uint2*)&Xb[arow0 + 24 * GXW + so];
                #pragma unroll
                for (int nt = 0; nt < 8; nt++) {
                    uint2 b = *(uint2*)&Wb[brow0 + nt * 8 * GXW + so];
                    mma16(c[0][nt], a0Lo.x, a0Hi.x, a0Lo.y, a0Hi.y, b.x, b.y);
                    mma16(c[1][nt], a1Lo.x, a1Hi.x, a1Lo.y, a1Hi.y, b.x, b.y);
                }
            }
        }
    }
}

// ---------------------------------------------------------------------------
// Fused QKV GEMM: gridDim.z = 3 selects {q,k,v} weight/bias/epilogue.
// ---------------------------------------------------------------------------
__global__ __launch_bounds__(256) void gemm_qkv(
    const uint32_t* __restrict__ xw, const uint32_t* __restrict__ wwall,
    const float* __restrict__ bq, const float* __restrict__ bk,
    const float* __restrict__ bv,
    const float* __restrict__ cosb, const float* __restrict__ sinb)
{
    extern __shared__ uint32_t gsh[];

    const int tid  = threadIdx.x;
    const int lane = tid & 31, wrp = tid >> 5;
    const int g = lane >> 2, q = lane & 3;
    const int wm = wrp & 3, wn = wrp >> 2;
    const int m0 = blockIdx.y * 128, n0 = blockIdx.x * 128;
    const int mode = blockIdx.z;

    const uint32_t* Ww = wwall + (size_t)mode * DMc * 384;
    const float* bias = (mode == 0) ? bq : (mode == 1) ? bk : bv;

    float c[2][8][4] = {};
    gemm_core(xw, Ww, gsh, m0, n0, tid,
              (wm * 32 + g) * GXW, (wn * 64 + g) * GXW, q, c);

    const int h = blockIdx.x * 2 + wn;
    const int nb = n0 + wn * 64;

    if (mode <= 1) {
        const float post = (mode == 0) ? (1.4426950408889634f / 64.0f) : 1.0f;
        #pragma unroll
        for (int mf = 0; mf < 2; mf++) {
            #pragma unroll
            for (int rr = 0; rr < 2; rr++) {
                int row = m0 + wm * 32 + mf * 16 + g + rr * 8;
                int bb = row >> 12, sg = row & (Sc - 1);
                size_t hb = (size_t)(bb * Hc + h) * Sc * 32;
                #pragma unroll
                for (int nt = 0; nt < 4; nt++) {
                    int d = nt * 8 + q * 2;
                    float lo0 = c[mf][nt][rr * 2 + 0]     + bias[nb + d];
                    float lo1 = c[mf][nt][rr * 2 + 1]     + bias[nb + d + 1];
                    float hi0 = c[mf][nt + 4][rr * 2 + 0] + bias[nb + d + 32];
                    float hi1 = c[mf][nt + 4][rr * 2 + 1] + bias[nb + d + 33];
                    float c0 = cosb[sg * HDc + d],     c1 = cosb[sg * HDc + d + 1];
                    float s0 = sinb[sg * HDc + d],     s1 = sinb[sg * HDc + d + 1];
                    float r0 = (lo0 * c0 - hi0 * s0) * post;
                    float r1 = (lo1 * c1 - hi1 * s1) * post;
                    float r2 = (hi0 * c0 + lo0 * s0) * post;
                    float r3 = (hi1 * c1 + lo1 * s1) * post;
                    if (mode == 0) {
                        size_t base = hb + (size_t)sg * 32;
                        g_qw[base + nt * 4 + q]      = packbf(r0, r1);
                        g_qw[base + nt * 4 + q + 16] = packbf(r2, r3);
                    } else {
                        int tile = sg >> 6, n = sg & 63;
                        size_t tb = hb + (size_t)tile * 2048;
                        int dp = nt * 4 + q;
                        int rrow = (dp >> 3) * 4 + (dp & 3);
                        int e = (dp >> 2) & 1;
                        g_kw[tb + rrow * 128 + 2 * n + e]       = packbf(r0, r1);
                        g_kw[tb + (rrow + 8) * 128 + 2 * n + e] = packbf(r2, r3);
                    }
                }
            }
        }
    } else {
        #pragma unroll
        for (int mf = 0; mf < 2; mf++) {
            #pragma unroll
            for (int rr = 0; rr < 2; rr++) {
                int row = m0 + wm * 32 + mf * 16 + g + rr * 8;
                int bb = row >> 12, sg = row & (Sc - 1);
                size_t hb = (size_t)(bb * Hc + h) * Sc * 32;
                int tile = sg >> 6;
                int jj = (sg >> 1) & 31;
                int rrow = (jj >> 3) * 4 + (jj & 3);
                int e = (jj >> 2) & 1;
                size_t bw = hb + (size_t)tile * 2048 + rrow * 128 + e;
                #pragma unroll
                for (int nt = 0; nt < 8; nt++) {
                    int d = nt * 8 + q * 2;
                    float v0 = c[mf][nt][rr * 2 + 0] + bias[nb + d];
                    float v1 = c[mf][nt][rr * 2 + 1] + bias[nb + d + 1];
                    float w0 = __shfl_down_sync(0xffffffffu, v0, 4);
                    float w1 = __shfl_down_sync(0xffffffffu, v1, 4);
                    if ((g & 1) == 0) {
                        g_vw[bw + 2 * d]       = packbf(v0, w0);
                        g_vw[bw + 2 * (d + 1)] = packbf(v1, w1);
                    }
                }
            }
        }
    }
}

// ---------------------------------------------------------------------------
// Out-projection GEMM + residual -> g_res (fp32)
// ---------------------------------------------------------------------------
__global__ __launch_bounds__(256) void gemm_out(
    const uint32_t* __restrict__ aw, const uint32_t* __restrict__ ww,
    const float* __restrict__ resid)
{
    extern __shared__ uint32_t gsh[];

    const int tid  = threadIdx.x;
    const int lane = tid & 31, wrp = tid >> 5;
    const int g = lane >> 2, q = lane & 3;
    const int wm = wrp & 3, wn = wrp >> 2;
    const int m0 = blockIdx.y * 128, n0 = blockIdx.x * 128;

    float c[2][8][4] = {};
    gemm_core(aw, ww, gsh, m0, n0, tid,
              (wm * 32 + g) * GXW, (wn * 64 + g) * GXW, q, c);

    const int nb = n0 + wn * 64;
    #pragma unroll
    for (int mf = 0; mf < 2; mf++) {
        #pragma unroll
        for (int rr = 0; rr < 2; rr++) {
            int row = m0 + wm * 32 + mf * 16 + g + rr * 8;
            #pragma unroll
            for (int nt = 0; nt < 8; nt++) {
                int col = nb + nt * 8 + q * 2;
                float2 r = *(const float2*)&resid[(size_t)row * DMc + col];
                *(float2*)&g_res[(size_t)row * DMc + col] =
                    make_float2(c[mf][nt][rr * 2 + 0] + r.x,
                                c[mf][nt][rr * 2 + 1] + r.y);
            }
        }
    }
}

// ---------------------------------------------------------------------------
// bf16 flash attention (unchanged; ~311 us)
// ---------------------------------------------------------------------------
constexpr int TSTRIDE = 136;
constexpr int TSZ = 16 * TSTRIDE;

__device__ __forceinline__ void ldt(const uint32_t* src_tile, uint32_t* dst, int tid) {
    #pragma unroll
    for (int p = 0; p < 2; p++) {
        int f = p * 256 + tid;
        int r = f >> 5, w4 = (f & 31) * 4;
        cp16(&dst[r * TSTRIDE + w4], &src_tile[f * 4]);
    }
}

__global__ __launch_bounds__(256, 2) void flash_mma()
{
    __shared__ uint32_t sh[4 * TSZ];
    uint32_t* K0 = sh;
    uint32_t* K1 = sh + TSZ;
    uint32_t* V0 = sh + 2 * TSZ;
    uint32_t* V1 = sh + 3 * TSZ;

    const int tid  = threadIdx.x;
    const int lane = tid & 31, wrp = tid >> 5;
    const int g = lane >> 2, q = lane & 3;
    const int bh = blockIdx.y, m0 = blockIdx.x * 128;

    const uint32_t* qw = g_qw + (size_t)bh * Sc * 32;
    const uint32_t* kw = g_kw + (size_t)bh * Sc * 32;
    const uint32_t* vw = g_vw + (size_t)bh * Sc * 32;

    ldt(kw, K0, tid);
    ldt(vw, V0, tid);
    cp_commit();
    ldt(kw + 2048, K1, tid);
    ldt(vw + 2048, V1, tid);
    cp_commit();

    uint32_t qa[4][4];
    {
        const uint32_t* q0 = qw + (size_t)(m0 + wrp * 16 + g) * 32;
        const uint32_t* q1 = q0 + 8 * 32;
        #pragma unroll
        for (int ks = 0; ks < 4; ks++) {
            qa[ks][0] = q0[8 * ks + q];
            qa[ks][1] = q1[8 * ks + q];
            qa[ks][2] = q0[8 * ks + q + 4];
            qa[ks][3] = q1[8 * ks + q + 4];
        }
    }

    cp_wait<1>();
    __syncthreads();

    float o[8][4] = {};
    float ps0 = 0.f, ps1 = 0.f;

    #pragma unroll 1
    for (int t = 0; t < Sc / 64; t++) {
        uint32_t* Ks = (t & 1) ? K1 : K0;
        uint32_t* Vs = (t & 1) ? V1 : V0;

        float s[8][4] = {};
        #pragma unroll
        for (int ks = 0; ks < 4; ks++) {
            #pragma unroll
            for (int nt = 0; nt < 8; nt++) {
                uint2 b = *(uint2*)&Ks[(ks * 4 + q) * TSTRIDE + 2 * (nt * 8 + g)];
                mma16(s[nt], qa[ks][0], qa[ks][1], qa[ks][2], qa[ks][3], b.x, b.y);
            }
        }

        uint32_t pk[8][2];
        #pragma unroll
        for (int nt = 0; nt < 8; nt++) {
            float e0 = ex2f(s[nt][0]);
            float e1 = ex2f(s[nt][1]);
            float e2 = ex2f(s[nt][2]);
            float e3 = ex2f(s[nt][3]);
            ps0 += e0 + e1;
            ps1 += e2 + e3;
            pk[nt][0] = packbf(e0, e1);
            pk[nt][1] = packbf(e2, e3);
        }

        #pragma unroll
        for (int ks = 0; ks < 4; ks++) {
            #pragma unroll
            for (int nt = 0; nt < 8; nt++) {
                uint2 b = *(uint2*)&Vs[(ks * 4 + q) * TSTRIDE + 2 * (nt * 8 + g)];
                mma16(o[nt], pk[2 * ks][0], pk[2 * ks][1],
                             pk[2 * ks + 1][0], pk[2 * ks + 1][1], b.x, b.y);
            }
        }

        if (t == Sc / 64 - 1) break;
        __syncthreads();
        if (t + 2 < Sc / 64) {
            uint32_t* Kd = (t & 1) ? K1 : K0;
            uint32_t* Vd = (t & 1) ? V1 : V0;
            ldt(kw + (size_t)(t + 2) * 2048, Kd, tid);
            ldt(vw + (size_t)(t + 2) * 2048, Vd, tid);
            cp_commit();
            cp_wait<1>();
        } else {
            cp_wait<0>();
        }
        __syncthreads();
    }

    ps0 += __shfl_xor_sync(0xffffffffu, ps0, 1);
    ps0 += __shfl_xor_sync(0xffffffffu, ps0, 2);
    ps1 += __shfl_xor_sync(0xffffffffu, ps1, 1);
    ps1 += __shfl_xor_sync(0xffffffffu, ps1, 2);
    float inv0 = 1.0f / ps0, inv1 = 1.0f / ps1;

    const int b = bh / Hc, h = bh % Hc;
    #pragma unroll
    for (int rr = 0; rr < 2; rr++) {
        int row = m0 + wrp * 16 + g + rr * 8;
        float inv = rr ? inv1 : inv0;
        size_t rb = (size_t)(b * Sc + row) * 24;
        #pragma unroll
        for (int nt = 0; nt < 8; nt++) {
            int kp = h * 32 + nt * 4 + q;
            int chunk = kp >> 4, slot = ppw(kp & 15);
            g_aw[(rb + chunk) * 16 + slot] =
                packbf(o[nt][rr * 2] * inv, o[nt][rr * 2 + 1] * inv);
        }
    }
}

// ---------------------------------------------------------------------------
// LayerNorm: one WARP per row. 8 rows/block.
// ---------------------------------------------------------------------------
__global__ __launch_bounds__(256) void ln_kernel(
    const float* __restrict__ gam, const float* __restrict__ bet,
    float* __restrict__ out)
{
    const int wid = threadIdx.x >> 5, lane = threadIdx.x & 31;
    const int row = blockIdx.x * 8 + wid;
    const float* x = g_res + (size_t)row * DMc;

    float4 v[6];
    float s = 0.f, sq = 0.f;
    #pragma unroll
    for (int i = 0; i < 6; i++) {
        v[i] = *(const float4*)&x[(i * 32 + lane) * 4];
        s  += v[i].x + v[i].y + v[i].z + v[i].w;
        sq += v[i].x * v[i].x + v[i].y * v[i].y
            + v[i].z * v[i].z + v[i].w * v[i].w;
    }
    #pragma unroll
    for (int off = 16; off >= 1; off >>= 1) {
        s  += __shfl_xor_sync(0xffffffffu, s,  off);
        sq += __shfl_xor_sync(0xffffffffu, sq, off);
    }
    const float inv_n = 1.0f / 768.0f;
    float mu  = s * inv_n;
    float var = sq * inv_n - mu * mu;
    float inv = rsqrtf(var + 1e-12f);

    float* op = out + (size_t)row * DMc;
    #pragma unroll
    for (int i = 0; i < 6; i++) {
        int e = (i * 32 + lane) * 4;
        float4 gm = *(const float4*)&gam[e];
        float4 bt = *(const float4*)&bet[e];
        *(float4*)&op[e] = make_float4(
            (v[i].x - mu) * inv * gm.x + bt.x,
            (v[i].y - mu) * inv * gm.y + bt.y,
            (v[i].z - mu) * inv * gm.z + bt.z,
            (v[i].w - mu) * inv * gm.w + bt.w);
    }
}

// ---------------------------------------------------------------------------
extern "C" void kernel_launch(void* const* d_in, const int* in_sizes, int n_in,
                              void* d_out, int out_size)
{
    const float* hidden = (const float*)d_in[0];
    const float* cosb   = (const float*)d_in[1];
    const float* sinb   = (const float*)d_in[2];
    const float* Wq     = (const float*)d_in[3];
    const float* bq     = (const float*)d_in[4];
    const float* Wk     = (const float*)d_in[5];
    const float* bk     = (const float*)d_in[6];
    const float* Wv     = (const float*)d_in[7];
    const float* bv     = (const float*)d_in[8];
    const float* Wo     = (const float*)d_in[9];
    const float* lng    = (const float*)d_in[10];
    const float* lnb    = (const float*)d_in[11];
    float* out = (float*)d_out;

    uint32_t* xw = nullptr; uint32_t* ww = nullptr; uint32_t* aw = nullptr;
    cudaGetSymbolAddress((void**)&xw, g_xw);
    cudaGetSymbolAddress((void**)&ww, g_ww);
    cudaGetSymbolAddress((void**)&aw, g_aw);

    const int pack_total = BSc * 192 + 4 * DMc * 192;
    pack_all<<<(pack_total + 255) / 256, 256>>>(hidden, Wq, Wk, Wv, Wo);

    const int gemm_smem = 4 * GBUF * (int)sizeof(uint32_t);  // 98304
    cudaFuncSetAttribute(gemm_qkv,
                         cudaFuncAttributeMaxDynamicSharedMemorySize, gemm_smem);
    cudaFuncSetAttribute(gemm_out,
                         cudaFuncAttributeMaxDynamicSharedMemorySize, gemm_smem);

    gemm_qkv<<<dim3(DMc / 128, BSc / 128, 3), 256, gemm_smem>>>(
        xw, ww, bq, bk, bv, cosb, sinb);

    flash_mma<<<dim3(Sc / 128, BHc), 256>>>();

    gemm_out<<<dim3(DMc / 128, BSc / 128), 256, gemm_smem>>>(
        aw, ww + (size_t)3 * DMc * 384, hidden);

    ln_kernel<<<BSc / 8, 256>>>(lng, lnb, out);
}